// round 2
// baseline (speedup 1.0000x reference)
#include <cuda_runtime.h>

// Problem constants
#define NB   2
#define SEQ  2048     // IN_SEQ = HID_SEQ = OUT_SEQ
#define CDIM 1024     // C_IN = C_OUT
#define NH   16
#define HD   64

// ---------------------------------------------------------------------------
// Static device scratch (allocation APIs are forbidden; __device__ globals OK)
// ---------------------------------------------------------------------------
__device__ float g_xh[(size_t)NB * SEQ * CDIM];            // 16 MB
__device__ float g_q [(size_t)NB * SEQ * CDIM];            // 16 MB  ([b,t,o] layout)
__device__ float g_k [(size_t)NB * SEQ * CDIM];            // 16 MB
__device__ float g_v [(size_t)NB * SEQ * CDIM];            // 16 MB
__device__ float g_attn[(size_t)NB * NH * SEQ * SEQ];      // 512 MB
__device__ float g_z [(size_t)NB * NH * SEQ * HD];         // 16 MB
__device__ float g_s [(size_t)NB * CDIM];                  // colsum of v

// ---------------------------------------------------------------------------
// Generic fp32 tiled GEMM: C = alpha * op(A) * op(B) (+ bias variants)
//   TA=0: A[m,k] row-major (lda = row stride). TA=1: A stored [K,M] (lda = row stride over k).
//   TB=0: B[k,n] row-major.                    TB=1: B stored [N,K].
//   BIAS: 0 none, 1 += bias1[m], 2 += bias1[n], 3 += bias1[m]*bias2[n]
//   Batch via blockIdx.z:  zo = z / zInner, zi = z % zInner; base += zo*s?o + zi*s?i
// Tile: BM=BN=64, BK=16, 256 threads, 4x4 per thread. Dims must divide evenly.
// ---------------------------------------------------------------------------
template <int TA, int TB, int BIAS>
__global__ void gemm64(const float* __restrict__ A, const float* __restrict__ B,
                       float* __restrict__ C,
                       int M, int N, int K, int lda, int ldb, int ldc,
                       long long sAo, long long sAi,
                       long long sBo, long long sBi,
                       long long sCo, long long sCi, int zInner,
                       const float* __restrict__ bias1,
                       const float* __restrict__ bias2,
                       long long sB2o, long long sB2i,
                       float alpha)
{
    __shared__ __align__(16) float As[16][68];
    __shared__ __align__(16) float Bs[16][68];

    int z = blockIdx.z;
    int zo = z / zInner, zi = z % zInner;
    A += zo * sAo + zi * sAi;
    B += zo * sBo + zi * sBi;
    C += zo * sCo + zi * sCi;
    const float* b2 = (BIAS == 3) ? (bias2 + zo * sB2o + zi * sB2i) : nullptr;

    int tid = threadIdx.x;
    int tx = tid & 15, ty = tid >> 4;
    int m0 = blockIdx.y * 64, n0 = blockIdx.x * 64;

    float acc[4][4] = {};

    for (int k0 = 0; k0 < K; k0 += 16) {
        // ---- load A tile into As[kk][m] ----
#pragma unroll
        for (int i = 0; i < 4; i++) {
            int li = tid + i * 256;
            if (TA == 0) {
                int kk = li & 15, m = li >> 4;
                As[kk][m] = A[(long long)(m0 + m) * lda + (k0 + kk)];
            } else {
                int m = li & 63, kk = li >> 6;
                As[kk][m] = A[(long long)(k0 + kk) * lda + (m0 + m)];
            }
        }
        // ---- load B tile into Bs[kk][n] ----
#pragma unroll
        for (int i = 0; i < 4; i++) {
            int li = tid + i * 256;
            if (TB == 0) {
                int n = li & 63, kk = li >> 6;
                Bs[kk][n] = B[(long long)(k0 + kk) * ldb + (n0 + n)];
            } else {
                int kk = li & 15, n = li >> 4;
                Bs[kk][n] = B[(long long)(n0 + n) * ldb + (k0 + kk)];
            }
        }
        __syncthreads();

#pragma unroll
        for (int kk = 0; kk < 16; kk++) {
            float4 av = *(const float4*)&As[kk][ty * 4];
            float4 bv = *(const float4*)&Bs[kk][tx * 4];
            float a[4] = {av.x, av.y, av.z, av.w};
            float b[4] = {bv.x, bv.y, bv.z, bv.w};
#pragma unroll
            for (int i = 0; i < 4; i++)
#pragma unroll
                for (int j = 0; j < 4; j++)
                    acc[i][j] += a[i] * b[j];
        }
        __syncthreads();
    }

#pragma unroll
    for (int i = 0; i < 4; i++) {
        int m = m0 + ty * 4 + i;
#pragma unroll
        for (int j = 0; j < 4; j++) {
            int n = n0 + tx * 4 + j;
            float v = alpha * acc[i][j];
            if (BIAS == 1) v += bias1[m];
            if (BIAS == 2) v += bias1[n];
            if (BIAS == 3) v += bias1[m] * b2[n];
            C[(long long)m * ldc + n] = v;
        }
    }
}

// ---------------------------------------------------------------------------
// Fast exp via FMA polynomial (avoids MUFU bottleneck: rt_SMSP=8 on sm_103a).
// Input x <= 0 (post max-subtraction), |error| ~ 2.4e-6 relative.
// ---------------------------------------------------------------------------
__device__ __forceinline__ float fexp(float x)
{
    float t = x * 1.4426950408889634f;      // x * log2(e)
    float k = rintf(t);
    float f = (t - k) * 0.6931471805599453f; // back to natural units, |f| <= 0.3466
    float p = 1.0f + f * (1.0f + f * (0.5f + f * (0.166666667f +
                     f * (0.0416666668f + f * 0.00833333340f))));
    return __int_as_float(((int)k + 127) << 23) * p;
}

// Row softmax over contiguous rows of length 2048. One block (256 thr) per row.
// All 8 elements/thread kept in registers -> exactly 1 read + 1 write of attn.
__global__ void softmax_rows(float* __restrict__ a)
{
    float* p = a + (long long)blockIdx.x * SEQ;
    int t = threadIdx.x;
    int w = t >> 5, lane = t & 31;

    float v[8];
    float m = -1e30f;
#pragma unroll
    for (int i = 0; i < 8; i++) {
        v[i] = p[t + i * 256];
        m = fmaxf(m, v[i]);
    }
#pragma unroll
    for (int o = 16; o; o >>= 1) m = fmaxf(m, __shfl_xor_sync(0xffffffffu, m, o));

    __shared__ float red[8];
    if (lane == 0) red[w] = m;
    __syncthreads();
    float bm = red[0];
#pragma unroll
    for (int i = 1; i < 8; i++) bm = fmaxf(bm, red[i]);
    __syncthreads();

    float s = 0.f;
#pragma unroll
    for (int i = 0; i < 8; i++) {
        v[i] = fexp(v[i] - bm);
        s += v[i];
    }
#pragma unroll
    for (int o = 16; o; o >>= 1) s += __shfl_xor_sync(0xffffffffu, s, o);
    if (lane == 0) red[w] = s;
    __syncthreads();
    float bs = red[0];
#pragma unroll
    for (int i = 1; i < 8; i++) bs += red[i];

    float inv = 1.0f / bs;
#pragma unroll
    for (int i = 0; i < 8; i++) p[t + i * 256] = v[i] * inv;
}

// S[b*CDIM + c] = sum_t v[b, t, c]   (v in [b, t, CDIM] layout)
__global__ void colsum_v(const float* __restrict__ v, float* __restrict__ s)
{
    int idx = blockIdx.x * blockDim.x + threadIdx.x;   // 0 .. NB*CDIM-1
    if (idx >= NB * CDIM) return;
    int b = idx >> 10, c = idx & (CDIM - 1);
    const float* p = v + (long long)b * SEQ * CDIM + c;
    float acc = 0.f;
#pragma unroll 8
    for (int t = 0; t < SEQ; t++) acc += p[(long long)t * CDIM];
    s[idx] = acc;
}

// ---------------------------------------------------------------------------
// Launch
// ---------------------------------------------------------------------------
extern "C" void kernel_launch(void* const* d_in, const int* in_sizes, int n_in,
                              void* d_out, int out_size)
{
    const float* x      = (const float*)d_in[0];
    const float* w_hseq = (const float*)d_in[1];
    const float* b_hseq = (const float*)d_in[2];
    const float* wq     = (const float*)d_in[3];
    const float* bq     = (const float*)d_in[4];
    const float* wk     = (const float*)d_in[5];
    const float* bk     = (const float*)d_in[6];
    const float* wv     = (const float*)d_in[7];
    const float* bv     = (const float*)d_in[8];
    const float* w_oseq = (const float*)d_in[9];
    const float* b_oseq = (const float*)d_in[10];
    float* out = (float*)d_out;

    float *xh, *q, *k, *v, *attn, *zbuf, *sv;
    cudaGetSymbolAddress((void**)&xh,   g_xh);
    cudaGetSymbolAddress((void**)&q,    g_q);
    cudaGetSymbolAddress((void**)&k,    g_k);
    cudaGetSymbolAddress((void**)&v,    g_v);
    cudaGetSymbolAddress((void**)&attn, g_attn);
    cudaGetSymbolAddress((void**)&zbuf, g_z);
    cudaGetSymbolAddress((void**)&sv,   g_s);

    const long long sBT  = (long long)SEQ * CDIM;      // [b] stride for [b,t,c]/[b,t,o]
    const long long sAh  = (long long)SEQ * SEQ;       // [h] stride for attn
    const long long sAb  = (long long)NH * SEQ * SEQ;  // [b] stride for attn
    const long long sZh  = (long long)SEQ * HD;        // [h] stride for z
    const long long sZb  = (long long)NH * SEQ * HD;   // [b] stride for z

    // Stage A: xh[b,t,c] = sum_s w_hseq[t,s] * x[b,s,c] + b_hseq[t]
    // M=2048(t), N=1024(c), K=2048(s), batch over b
    gemm64<0, 0, 1><<<dim3(CDIM / 64, SEQ / 64, NB), 256>>>(
        w_hseq, x, xh, SEQ, CDIM, SEQ, SEQ, CDIM, CDIM,
        0, 0, sBT, 0, sBT, 0, 1, b_hseq, nullptr, 0, 0, 1.0f);

    // Stage B: q/k/v[b,t,o] = xh[b,t,:] @ W^T + bias   (M=B*SEQ=4096, N=1024, K=1024)
    gemm64<0, 1, 2><<<dim3(CDIM / 64, (NB * SEQ) / 64, 1), 256>>>(
        xh, wq, q, NB * SEQ, CDIM, CDIM, CDIM, CDIM, CDIM,
        0, 0, 0, 0, 0, 0, 1, bq, nullptr, 0, 0, 1.0f);
    gemm64<0, 1, 2><<<dim3(CDIM / 64, (NB * SEQ) / 64, 1), 256>>>(
        xh, wk, k, NB * SEQ, CDIM, CDIM, CDIM, CDIM, CDIM,
        0, 0, 0, 0, 0, 0, 1, bk, nullptr, 0, 0, 1.0f);
    gemm64<0, 1, 2><<<dim3(CDIM / 64, (NB * SEQ) / 64, 1), 256>>>(
        xh, wv, v, NB * SEQ, CDIM, CDIM, CDIM, CDIM, CDIM,
        0, 0, 0, 0, 0, 0, 1, bv, nullptr, 0, 0, 1.0f);

    // Stage C: scores[b,h,qi,kj] = (1/8) * sum_d q[b,qi,h*64+d] * k[b,kj,h*64+d]
    // M=N=2048, K=64, batch z = b*16+h (zInner=16)
    gemm64<0, 1, 0><<<dim3(SEQ / 64, SEQ / 64, NB * NH), 256>>>(
        q, k, attn, SEQ, SEQ, HD, CDIM, CDIM, SEQ,
        sBT, HD, sBT, HD, sAb, sAh, NH, nullptr, nullptr, 0, 0, 0.125f);

    // Stage D: row softmax over k (one pass, register-resident)
    softmax_rows<<<NB * NH * SEQ, 256>>>(attn);

    // Column sums of v for the b_oseq bias term
    colsum_v<<<(NB * CDIM + 255) / 256, 256>>>(v, sv);

    // Stage E: Z[b,h,kj,d] = sum_qi attn[b,h,qi,kj] * v[b,qi,h*64+d]
    // M=2048(kj), N=64(d), K=2048(qi); A is attn^T (TA=1)
    gemm64<1, 0, 0><<<dim3(1, SEQ / 64, NB * NH), 256>>>(
        attn, v, zbuf, SEQ, HD, SEQ, SEQ, CDIM, HD,
        sAb, sAh, sBT, HD, sZb, sZh, NH, nullptr, nullptr, 0, 0, 1.0f);

    // Stage F: out[b,o,h*64+d] = sum_k w_oseq[o,k]*Z[b,h,k,d] + b_oseq[o]*S[b,h*64+d]
    // M=2048(o), N=64(d), K=2048(k)
    gemm64<0, 0, 3><<<dim3(1, SEQ / 64, NB * NH), 256>>>(
        w_oseq, zbuf, out, SEQ, HD, SEQ, SEQ, HD, CDIM,
        0, 0, sZb, sZh, sBT, HD, NH, b_oseq, sv, CDIM, HD, 1.0f);
}

// round 4
// speedup vs baseline: 1.8904x; 1.8904x over previous
#include <cuda_runtime.h>
#include <cstdint>

// Problem constants
#define NB_   2
#define SEQ  2048     // IN_SEQ = HID_SEQ = OUT_SEQ
#define CDIM 1024     // C_IN = C_OUT
#define NH   16
#define HD   64

// ---------------------------------------------------------------------------
// Static device scratch (allocation APIs are forbidden; __device__ globals OK)
// ---------------------------------------------------------------------------
__device__ float g_xh[(size_t)NB_ * SEQ * CDIM];           // 16 MB
__device__ float g_q [(size_t)NB_ * SEQ * CDIM];           // 16 MB  ([b,t,o] layout)
__device__ float g_k [(size_t)NB_ * SEQ * CDIM];           // 16 MB
__device__ float g_v [(size_t)NB_ * SEQ * CDIM];           // 16 MB
__device__ float g_attn[(size_t)NB_ * NH * SEQ * SEQ];     // 512 MB
__device__ float g_z [(size_t)NB_ * NH * SEQ * HD];        // 16 MB
__device__ float g_s [(size_t)NB_ * CDIM];                 // colsum of v

// ---------------------------------------------------------------------------
// Warp-level tensor-core primitives (base compute_103 features: sm_75/80-era)
// ---------------------------------------------------------------------------
__device__ __forceinline__ uint32_t smem_u32(const void* p) {
    uint32_t a;
    asm("{ .reg .u64 t; cvta.to.shared.u64 t, %1; cvt.u32.u64 %0, t; }" : "=r"(a) : "l"(p));
    return a;
}

__device__ __forceinline__ void ldsm_x4(uint32_t (&r)[4], uint32_t addr) {
    asm volatile("ldmatrix.sync.aligned.m8n8.x4.shared.b16 {%0,%1,%2,%3}, [%4];"
                 : "=r"(r[0]), "=r"(r[1]), "=r"(r[2]), "=r"(r[3]) : "r"(addr));
}
__device__ __forceinline__ void ldsm_x2(uint32_t (&r)[2], uint32_t addr) {
    asm volatile("ldmatrix.sync.aligned.m8n8.x2.shared.b16 {%0,%1}, [%2];"
                 : "=r"(r[0]), "=r"(r[1]) : "r"(addr));
}

__device__ __forceinline__ void mma16816(float (&c)[4], const uint32_t (&a)[4],
                                         const uint32_t (&b)[2]) {
    asm volatile(
        "mma.sync.aligned.m16n8k16.row.col.f32.bf16.bf16.f32 "
        "{%0,%1,%2,%3}, {%4,%5,%6,%7}, {%8,%9}, {%0,%1,%2,%3};"
        : "+f"(c[0]), "+f"(c[1]), "+f"(c[2]), "+f"(c[3])
        : "r"(a[0]), "r"(a[1]), "r"(a[2]), "r"(a[3]), "r"(b[0]), "r"(b[1]));
}

// fp32 -> (bf16 hi, bf16 lo) split, two elements at a time
__device__ __forceinline__ void split2(float x0, float x1, uint32_t& hi2, uint32_t& lo2)
{
    asm("cvt.rn.bf16x2.f32 %0, %1, %2;" : "=r"(hi2) : "f"(x1), "f"(x0));
    float h0 = __uint_as_float(hi2 << 16);
    float h1 = __uint_as_float(hi2 & 0xffff0000u);
    asm("cvt.rn.bf16x2.f32 %0, %1, %2;" : "=r"(lo2) : "f"(x1 - h1), "f"(x0 - h0));
}

// ---------------------------------------------------------------------------
// Tensor-core bf16x3 GEMM:  C[m,n] = alpha * sum_k A[m,k]*B[n,k]  (+ bias)
//   CTA tile 128 x BN, K-chunk 32, double-buffered smem, register prefetch.
//   TA=0: A gmem [m,k] (lda = k-stride).  TA=1: A gmem [k,m] (lda = m-stride).
//   TB=1: B gmem [n,k].                    TB=0: B gmem [k,n].
//   BIAS: 0 none, 1 +=bias1[m], 2 +=bias1[n], 3 +=bias1[m]*bias2[n]
//   Smem rows padded to 40 halves (80 B): conflict-free for ldmatrix.
// ---------------------------------------------------------------------------
template <int TA, int TB, int BIAS, int BN>
__global__ void __launch_bounds__(256)
tgemm(const float* __restrict__ A, const float* __restrict__ B, float* __restrict__ C,
      int M, int N, int K, int lda, int ldb, int ldc,
      long long sAo, long long sAi, long long sBo, long long sBi,
      long long sCo, long long sCi, int zInner,
      const float* __restrict__ bias1, const float* __restrict__ bias2,
      long long sB2o, long long sB2i, float alpha)
{
    extern __shared__ char smem[];
    constexpr int BM = 128, BK = 32;
    constexpr int ROWB = 80;                       // bytes per smem row (40 halves)
    constexpr int A_BYTES = BM * ROWB;             // 10240
    constexpr int B_BYTES = BN * ROWB;
    constexpr int OFF_AL = A_BYTES;
    constexpr int OFF_BH = 2 * A_BYTES;
    constexpr int OFF_BL = 2 * A_BYTES + B_BYTES;
    constexpr int SBUF   = 2 * A_BYTES + 2 * B_BYTES;
    constexpr int NAR = 8;                         // A staging regs (hi) per thread
    constexpr int NBR = BN / 16;                   // B staging regs (hi) per thread
    constexpr int MI = (BN == 128) ? 4 : 2;        // m16 tiles per warp
    constexpr int NI = 4;                          // n8 tiles per warp
    constexpr int WM = (BN == 128) ? 2 : 4;        // warps along M

    const int tid = threadIdx.x;
    const int lane = tid & 31, wid = tid >> 5;
    const int warp_m = wid % WM, warp_n = wid / WM;
    const int m_base = warp_m * MI * 16;
    const int n_base = warp_n * NI * 8;

    int z = blockIdx.z, zo = z / zInner, zi = z % zInner;
    A += zo * sAo + zi * sAi;
    B += zo * sBo + zi * sBi;
    C += zo * sCo + zi * sCi;
    const float* b2 = (BIAS == 3) ? (bias2 + zo * sB2o + zi * sB2i) : nullptr;

    const int m0 = blockIdx.y * BM;
    const int n0 = blockIdx.x * BN;

    uint32_t sAh[NAR], sAl[NAR], sBh[NBR], sBl[NBR];

    // ---- LDG + split into registers ----
    auto load_A = [&](int k0) {
        if (TA == 0) {
#pragma unroll
            for (int it = 0; it < 8; ++it) {
                int idx = tid + it * 256, r = idx >> 4, p = idx & 15;
                float2 v = *reinterpret_cast<const float2*>(
                    A + (long long)(m0 + r) * lda + k0 + 2 * p);
                split2(v.x, v.y, sAh[it], sAl[it]);
            }
        } else {
#pragma unroll
            for (int it = 0; it < 2; ++it) {
                int idx = tid + it * 256, r = idx & 127, g = idx >> 7;
                const float* gp = A + (long long)(k0 + g * 8) * lda + (m0 + r);
                float x[8];
#pragma unroll
                for (int j = 0; j < 8; ++j) x[j] = gp[(long long)j * lda];
#pragma unroll
                for (int j = 0; j < 4; ++j)
                    split2(x[2 * j], x[2 * j + 1], sAh[it * 4 + j], sAl[it * 4 + j]);
            }
        }
    };
    auto load_B = [&](int k0) {
        if (TB == 1) {
#pragma unroll
            for (int it = 0; it < NBR; ++it) {
                int idx = tid + it * 256, r = idx >> 4, p = idx & 15;
                float2 v = *reinterpret_cast<const float2*>(
                    B + (long long)(n0 + r) * ldb + k0 + 2 * p);
                split2(v.x, v.y, sBh[it], sBl[it]);
            }
        } else {
#pragma unroll
            for (int it = 0; it < NBR / 4; ++it) {
                int idx = tid + it * 256, r = idx & (BN - 1), g = idx / BN;
                const float* gp = B + (long long)(k0 + g * 8) * ldb + (n0 + r);
                float x[8];
#pragma unroll
                for (int j = 0; j < 8; ++j) x[j] = gp[(long long)j * ldb];
#pragma unroll
                for (int j = 0; j < 4; ++j)
                    split2(x[2 * j], x[2 * j + 1], sBh[it * 4 + j], sBl[it * 4 + j]);
            }
        }
    };
    // ---- registers -> smem ----
    auto sts_A = [&](char* base) {
        if (TA == 0) {
#pragma unroll
            for (int it = 0; it < 8; ++it) {
                int idx = tid + it * 256, r = idx >> 4, p = idx & 15;
                *reinterpret_cast<uint32_t*>(base + r * ROWB + p * 4) = sAh[it];
                *reinterpret_cast<uint32_t*>(base + OFF_AL + r * ROWB + p * 4) = sAl[it];
            }
        } else {
#pragma unroll
            for (int it = 0; it < 2; ++it) {
                int idx = tid + it * 256, r = idx & 127, g = idx >> 7;
                *reinterpret_cast<uint4*>(base + r * ROWB + g * 16) =
                    make_uint4(sAh[it * 4], sAh[it * 4 + 1], sAh[it * 4 + 2], sAh[it * 4 + 3]);
                *reinterpret_cast<uint4*>(base + OFF_AL + r * ROWB + g * 16) =
                    make_uint4(sAl[it * 4], sAl[it * 4 + 1], sAl[it * 4 + 2], sAl[it * 4 + 3]);
            }
        }
    };
    auto sts_B = [&](char* base) {
        if (TB == 1) {
#pragma unroll
            for (int it = 0; it < NBR; ++it) {
                int idx = tid + it * 256, r = idx >> 4, p = idx & 15;
                *reinterpret_cast<uint32_t*>(base + OFF_BH + r * ROWB + p * 4) = sBh[it];
                *reinterpret_cast<uint32_t*>(base + OFF_BL + r * ROWB + p * 4) = sBl[it];
            }
        } else {
#pragma unroll
            for (int it = 0; it < NBR / 4; ++it) {
                int idx = tid + it * 256, r = idx & (BN - 1), g = idx / BN;
                *reinterpret_cast<uint4*>(base + OFF_BH + r * ROWB + g * 16) =
                    make_uint4(sBh[it * 4], sBh[it * 4 + 1], sBh[it * 4 + 2], sBh[it * 4 + 3]);
                *reinterpret_cast<uint4*>(base + OFF_BL + r * ROWB + g * 16) =
                    make_uint4(sBl[it * 4], sBl[it * 4 + 1], sBl[it * 4 + 2], sBl[it * 4 + 3]);
            }
        }
    };

    float acc[MI][NI][4] = {};

    char* buf0 = smem;
    char* buf1 = smem + SBUF;

    load_A(0); load_B(0);
    sts_A(buf0); sts_B(buf0);
    __syncthreads();

    const int nch = K / BK;
    for (int c = 0; c < nch; ++c) {
        char* cur = (c & 1) ? buf1 : buf0;
        char* nxt = (c & 1) ? buf0 : buf1;
        if (c + 1 < nch) { load_A((c + 1) * BK); load_B((c + 1) * BK); }

        const uint32_t cb = smem_u32(cur);
#pragma unroll
        for (int ks = 0; ks < 2; ++ks) {
            const int kk = ks * 16;
            uint32_t bh[NI][2], bl[NI][2];
#pragma unroll
            for (int ni = 0; ni < NI; ++ni) {
                uint32_t addr = cb + OFF_BH +
                    (n_base + ni * 8 + (lane & 7)) * ROWB + (kk + ((lane >> 3) & 1) * 8) * 2;
                ldsm_x2(bh[ni], addr);
                ldsm_x2(bl[ni], addr + (OFF_BL - OFF_BH));
            }
#pragma unroll
            for (int mi = 0; mi < MI; ++mi) {
                uint32_t ad = cb +
                    (m_base + mi * 16 + (lane & 15)) * ROWB + (kk + (lane >> 4) * 8) * 2;
                uint32_t ah[4], al[4];
                ldsm_x4(ah, ad);
                ldsm_x4(al, ad + OFF_AL);
#pragma unroll
                for (int ni = 0; ni < NI; ++ni) {
                    mma16816(acc[mi][ni], ah, bh[ni]);
                    mma16816(acc[mi][ni], ah, bl[ni]);
                    mma16816(acc[mi][ni], al, bh[ni]);
                }
            }
        }

        if (c + 1 < nch) {
            __syncthreads();          // all warps done reading nxt's old data
            sts_A(nxt); sts_B(nxt);
            __syncthreads();          // nxt ready for next iteration
        }
    }

    // ---- epilogue: registers -> gmem (float2 per store, 32B sectors) ----
#pragma unroll
    for (int mi = 0; mi < MI; ++mi) {
#pragma unroll
        for (int ni = 0; ni < NI; ++ni) {
            int m = m0 + m_base + mi * 16 + (lane >> 2);
            int n = n0 + n_base + ni * 8 + 2 * (lane & 3);
            float v0 = acc[mi][ni][0] * alpha, v1 = acc[mi][ni][1] * alpha;
            float v2 = acc[mi][ni][2] * alpha, v3 = acc[mi][ni][3] * alpha;
            if (BIAS == 1) { float b = bias1[m], bb = bias1[m + 8]; v0 += b; v1 += b; v2 += bb; v3 += bb; }
            if (BIAS == 2) { float b = bias1[n], bb = bias1[n + 1]; v0 += b; v1 += bb; v2 += b; v3 += bb; }
            if (BIAS == 3) {
                float c0 = b2[n], c1 = b2[n + 1];
                float bm = bias1[m], bm8 = bias1[m + 8];
                v0 += bm * c0; v1 += bm * c1; v2 += bm8 * c0; v3 += bm8 * c1;
            }
            *reinterpret_cast<float2*>(&C[(long long)m * ldc + n]) = make_float2(v0, v1);
            *reinterpret_cast<float2*>(&C[(long long)(m + 8) * ldc + n]) = make_float2(v2, v3);
        }
    }
}

// ---------------------------------------------------------------------------
// Fast exp via FMA polynomial (MUFU rt_SMSP=8 on sm_103a would bottleneck).
// ---------------------------------------------------------------------------
__device__ __forceinline__ float fexp(float x)
{
    float t = x * 1.4426950408889634f;
    float k = rintf(t);
    float f = (t - k) * 0.6931471805599453f;
    float p = 1.0f + f * (1.0f + f * (0.5f + f * (0.166666667f +
                     f * (0.0416666668f + f * 0.00833333340f))));
    return __int_as_float(((int)k + 127) << 23) * p;
}

// Row softmax over contiguous rows of length 2048. One block (256 thr) per row.
__global__ void softmax_rows(float* __restrict__ a)
{
    float* p = a + (long long)blockIdx.x * SEQ;
    int t = threadIdx.x;
    int w = t >> 5, lane = t & 31;

    float v[8];
    float m = -1e30f;
#pragma unroll
    for (int i = 0; i < 8; i++) {
        v[i] = p[t + i * 256];
        m = fmaxf(m, v[i]);
    }
#pragma unroll
    for (int o = 16; o; o >>= 1) m = fmaxf(m, __shfl_xor_sync(0xffffffffu, m, o));

    __shared__ float red[8];
    if (lane == 0) red[w] = m;
    __syncthreads();
    float bm = red[0];
#pragma unroll
    for (int i = 1; i < 8; i++) bm = fmaxf(bm, red[i]);
    __syncthreads();

    float s = 0.f;
#pragma unroll
    for (int i = 0; i < 8; i++) {
        v[i] = fexp(v[i] - bm);
        s += v[i];
    }
#pragma unroll
    for (int o = 16; o; o >>= 1) s += __shfl_xor_sync(0xffffffffu, s, o);
    if (lane == 0) red[w] = s;
    __syncthreads();
    float bs = red[0];
#pragma unroll
    for (int i = 1; i < 8; i++) bs += red[i];

    float inv = 1.0f / bs;
#pragma unroll
    for (int i = 0; i < 8; i++) p[t + i * 256] = v[i] * inv;
}

// S[b*CDIM + c] = sum_t v[b, t, c]
__global__ void colsum_v(const float* __restrict__ v, float* __restrict__ s)
{
    int idx = blockIdx.x * blockDim.x + threadIdx.x;
    if (idx >= NB_ * CDIM) return;
    int b = idx >> 10, c = idx & (CDIM - 1);
    const float* p = v + (long long)b * SEQ * CDIM + c;
    float acc = 0.f;
#pragma unroll 8
    for (int t = 0; t < SEQ; t++) acc += p[(long long)t * CDIM];
    s[idx] = acc;
}

// ---------------------------------------------------------------------------
// Launch
// ---------------------------------------------------------------------------
extern "C" void kernel_launch(void* const* d_in, const int* in_sizes, int n_in,
                              void* d_out, int out_size)
{
    const float* x      = (const float*)d_in[0];
    const float* w_hseq = (const float*)d_in[1];
    const float* b_hseq = (const float*)d_in[2];
    const float* wq     = (const float*)d_in[3];
    const float* bq     = (const float*)d_in[4];
    const float* wk     = (const float*)d_in[5];
    const float* bk     = (const float*)d_in[6];
    const float* wv     = (const float*)d_in[7];
    const float* bv     = (const float*)d_in[8];
    const float* w_oseq = (const float*)d_in[9];
    const float* b_oseq = (const float*)d_in[10];
    float* out = (float*)d_out;

    float *xh, *q, *k, *v, *attn, *zbuf, *sv;
    cudaGetSymbolAddress((void**)&xh,   g_xh);
    cudaGetSymbolAddress((void**)&q,    g_q);
    cudaGetSymbolAddress((void**)&k,    g_k);
    cudaGetSymbolAddress((void**)&v,    g_v);
    cudaGetSymbolAddress((void**)&attn, g_attn);
    cudaGetSymbolAddress((void**)&zbuf, g_z);
    cudaGetSymbolAddress((void**)&sv,   g_s);

    const long long sBT = (long long)SEQ * CDIM;
    const long long sAh = (long long)SEQ * SEQ;
    const long long sAb = (long long)NH * SEQ * SEQ;
    const long long sZh = (long long)SEQ * HD;
    const long long sZb = (long long)NH * SEQ * HD;

    // dynamic smem: 2 buffers of (2*A + 2*B) with 80-byte rows
    const int SM128 = 2 * (2 * 128 * 80 + 2 * 128 * 80);   // 81920
    const int SM64  = 2 * (2 * 128 * 80 + 2 * 64 * 80);    // 61440

    cudaFuncSetAttribute(tgemm<0, 0, 1, 128>, cudaFuncAttributeMaxDynamicSharedMemorySize, SM128);
    cudaFuncSetAttribute(tgemm<0, 1, 2, 128>, cudaFuncAttributeMaxDynamicSharedMemorySize, SM128);
    cudaFuncSetAttribute(tgemm<0, 1, 0, 128>, cudaFuncAttributeMaxDynamicSharedMemorySize, SM128);
    cudaFuncSetAttribute(tgemm<1, 0, 0, 64>,  cudaFuncAttributeMaxDynamicSharedMemorySize, SM64);
    cudaFuncSetAttribute(tgemm<0, 0, 3, 64>,  cudaFuncAttributeMaxDynamicSharedMemorySize, SM64);

    // Stage A: xh[b,t,c] = sum_s w_hseq[t,s] * x[b,s,c] + b_hseq[t]
    tgemm<0, 0, 1, 128><<<dim3(CDIM / 128, SEQ / 128, NB_), 256, SM128>>>(
        w_hseq, x, xh, SEQ, CDIM, SEQ, SEQ, CDIM, CDIM,
        0, 0, sBT, 0, sBT, 0, 1, b_hseq, nullptr, 0, 0, 1.0f);

    // Stage B: q/k/v[b,t,o] = xh @ W^T + bias
    tgemm<0, 1, 2, 128><<<dim3(CDIM / 128, (NB_ * SEQ) / 128, 1), 256, SM128>>>(
        xh, wq, q, NB_ * SEQ, CDIM, CDIM, CDIM, CDIM, CDIM,
        0, 0, 0, 0, 0, 0, 1, bq, nullptr, 0, 0, 1.0f);
    tgemm<0, 1, 2, 128><<<dim3(CDIM / 128, (NB_ * SEQ) / 128, 1), 256, SM128>>>(
        xh, wk, k, NB_ * SEQ, CDIM, CDIM, CDIM, CDIM, CDIM,
        0, 0, 0, 0, 0, 0, 1, bk, nullptr, 0, 0, 1.0f);
    tgemm<0, 1, 2, 128><<<dim3(CDIM / 128, (NB_ * SEQ) / 128, 1), 256, SM128>>>(
        xh, wv, v, NB_ * SEQ, CDIM, CDIM, CDIM, CDIM, CDIM,
        0, 0, 0, 0, 0, 0, 1, bv, nullptr, 0, 0, 1.0f);

    // Stage C: scores[b,h,qi,kj] = (1/8) q . k   (K = 64 per head)
    tgemm<0, 1, 0, 128><<<dim3(SEQ / 128, SEQ / 128, NB_ * NH), 256, SM128>>>(
        q, k, attn, SEQ, SEQ, HD, CDIM, CDIM, SEQ,
        sBT, HD, sBT, HD, sAb, sAh, NH, nullptr, nullptr, 0, 0, 0.125f);

    // Stage D: row softmax over k
    softmax_rows<<<NB_ * NH * SEQ, 256>>>(attn);

    // Column sums of v (for the b_oseq rank-1 term)
    colsum_v<<<(NB_ * CDIM + 255) / 256, 256>>>(v, sv);

    // Stage E: Z[b,h,kj,d] = sum_qi attn[b,h,qi,kj] * v[b,qi,h*64+d]
    tgemm<1, 0, 0, 64><<<dim3(1, SEQ / 128, NB_ * NH), 256, SM64>>>(
        attn, v, zbuf, SEQ, HD, SEQ, SEQ, CDIM, HD,
        sAb, sAh, sBT, HD, sZb, sZh, NH, nullptr, nullptr, 0, 0, 1.0f);

    // Stage F: out[b,o,h*64+d] = sum_k w_oseq[o,k]*Z[b,h,k,d] + b_oseq[o]*S[b,h*64+d]
    tgemm<0, 0, 3, 64><<<dim3(1, SEQ / 128, NB_ * NH), 256, SM64>>>(
        w_oseq, zbuf, out, SEQ, HD, SEQ, SEQ, HD, CDIM,
        0, 0, sZb, sZh, sBT, HD, NH, b_oseq, sv, CDIM, HD, 1.0f);
}

// round 5
// speedup vs baseline: 2.3827x; 1.2604x over previous
#include <cuda_runtime.h>
#include <cuda_bf16.h>
#include <cstdint>

// Problem constants
#define NB_   2
#define SEQ  2048
#define CDIM 1024
#define NH   16
#define HD   64

// ---------------------------------------------------------------------------
// Static device scratch (bf16 hi/lo pairs for all GEMM operands)
// ---------------------------------------------------------------------------
#define E_X   ((size_t)NB_ * SEQ * CDIM)      // 4M elems
#define E_WS  ((size_t)SEQ * SEQ)             // 4M
#define E_W   ((size_t)CDIM * CDIM)           // 1M
#define E_P   ((size_t)NB_ * NH * SEQ * SEQ)  // 134M
#define E_Z   ((size_t)NB_ * NH * SEQ * HD)   // 4M

__device__ __nv_bfloat16 g_xb_h[E_X],  g_xb_l[E_X];
__device__ __nv_bfloat16 g_whs_h[E_WS], g_whs_l[E_WS];
__device__ __nv_bfloat16 g_wq_h[E_W],  g_wq_l[E_W];
__device__ __nv_bfloat16 g_wk_h[E_W],  g_wk_l[E_W];
__device__ __nv_bfloat16 g_wv_h[E_W],  g_wv_l[E_W];
__device__ __nv_bfloat16 g_wo_h[E_WS], g_wo_l[E_WS];
__device__ __nv_bfloat16 g_xh_h[E_X],  g_xh_l[E_X];
__device__ __nv_bfloat16 g_q_h[E_X],   g_q_l[E_X];
__device__ __nv_bfloat16 g_k_h[E_X],   g_k_l[E_X];
__device__ __nv_bfloat16 g_v_h[E_X],   g_v_l[E_X];
__device__ float         g_attn[E_P];               // fp32 scores (512 MB)
__device__ __nv_bfloat16 g_p_h[E_P],   g_p_l[E_P];  // softmax probs (512 MB)
__device__ __nv_bfloat16 g_z_h[E_Z],   g_z_l[E_Z];
__device__ float         g_s[(size_t)NB_ * CDIM];   // colsum of v

// ---------------------------------------------------------------------------
// Primitives
// ---------------------------------------------------------------------------
__device__ __forceinline__ uint32_t smem_u32(const void* p) {
    uint32_t a;
    asm("{ .reg .u64 t; cvta.to.shared.u64 t, %1; cvt.u32.u64 %0, t; }" : "=r"(a) : "l"(p));
    return a;
}
#define CP16(d, s) asm volatile("cp.async.cg.shared.global [%0], [%1], 16;" :: "r"(d), "l"(s))
#define CP_COMMIT() asm volatile("cp.async.commit_group;" ::: "memory")
#define CP_WAIT1()  asm volatile("cp.async.wait_group 1;" ::: "memory")

__device__ __forceinline__ void ldsm_x4(uint32_t (&r)[4], uint32_t addr) {
    asm volatile("ldmatrix.sync.aligned.m8n8.x4.shared.b16 {%0,%1,%2,%3}, [%4];"
                 : "=r"(r[0]), "=r"(r[1]), "=r"(r[2]), "=r"(r[3]) : "r"(addr));
}
__device__ __forceinline__ void ldsm_x4_t(uint32_t (&r)[4], uint32_t addr) {
    asm volatile("ldmatrix.sync.aligned.m8n8.x4.trans.shared.b16 {%0,%1,%2,%3}, [%4];"
                 : "=r"(r[0]), "=r"(r[1]), "=r"(r[2]), "=r"(r[3]) : "r"(addr));
}
__device__ __forceinline__ void ldsm_x2(uint32_t (&r)[2], uint32_t addr) {
    asm volatile("ldmatrix.sync.aligned.m8n8.x2.shared.b16 {%0,%1}, [%2];"
                 : "=r"(r[0]), "=r"(r[1]) : "r"(addr));
}
__device__ __forceinline__ void ldsm_x2_t(uint32_t (&r)[2], uint32_t addr) {
    asm volatile("ldmatrix.sync.aligned.m8n8.x2.trans.shared.b16 {%0,%1}, [%2];"
                 : "=r"(r[0]), "=r"(r[1]) : "r"(addr));
}
__device__ __forceinline__ void mma16816(float (&c)[4], const uint32_t (&a)[4],
                                         const uint32_t (&b)[2]) {
    asm volatile(
        "mma.sync.aligned.m16n8k16.row.col.f32.bf16.bf16.f32 "
        "{%0,%1,%2,%3}, {%4,%5,%6,%7}, {%8,%9}, {%0,%1,%2,%3};"
        : "+f"(c[0]), "+f"(c[1]), "+f"(c[2]), "+f"(c[3])
        : "r"(a[0]), "r"(a[1]), "r"(a[2]), "r"(a[3]), "r"(b[0]), "r"(b[1]));
}

// fp32 -> (bf16 hi, bf16 lo) split, two elements at a time
__device__ __forceinline__ void split2(float x0, float x1, uint32_t& hi2, uint32_t& lo2)
{
    asm("cvt.rn.bf16x2.f32 %0, %1, %2;" : "=r"(hi2) : "f"(x1), "f"(x0));
    float h0 = __uint_as_float(hi2 << 16);
    float h1 = __uint_as_float(hi2 & 0xffff0000u);
    asm("cvt.rn.bf16x2.f32 %0, %1, %2;" : "=r"(lo2) : "f"(x1 - h1), "f"(x0 - h0));
}

// ---------------------------------------------------------------------------
// fp32 -> bf16 hi/lo conversion (inputs & weights), float4 granularity
// ---------------------------------------------------------------------------
__global__ void convert_split(const float* __restrict__ src,
                              __nv_bfloat16* __restrict__ hi,
                              __nv_bfloat16* __restrict__ lo, int n4)
{
    int i = blockIdx.x * blockDim.x + threadIdx.x;
    if (i >= n4) return;
    float4 v = reinterpret_cast<const float4*>(src)[i];
    uint32_t h0, l0, h1, l1;
    split2(v.x, v.y, h0, l0);
    split2(v.z, v.w, h1, l1);
    reinterpret_cast<uint2*>(hi)[i] = make_uint2(h0, h1);
    reinterpret_cast<uint2*>(lo)[i] = make_uint2(l0, l1);
}

// ---------------------------------------------------------------------------
// Tensor-core bf16x3 GEMM, all operands pre-split bf16 hi/lo.
//   C[m,n] = alpha * sum_k A[m,k]*B[n,k]  (+ bias), fp32 accumulate.
//   TA=0: A gmem [m,k] (lda=k-stride).  TA=1: A gmem [k,m] (lda=m-stride).
//   TB=1: B gmem [n,k].                  TB=0: B gmem [k,n].
//   OUT=0: fp32 C.  OUT=1: bf16 hi/lo pair C.
//   2-stage cp.async pipeline, BM=128 x BN, BK=32, 256 thr, 2 CTAs/SM.
// ---------------------------------------------------------------------------
template <int TA, int TB, int BIAS, int BN, int OUT>
__global__ void __launch_bounds__(256, 2)
tgemm(const __nv_bfloat16* __restrict__ Ah_, const __nv_bfloat16* __restrict__ Al_,
      const __nv_bfloat16* __restrict__ Bh_, const __nv_bfloat16* __restrict__ Bl_,
      float* __restrict__ Cf,
      __nv_bfloat16* __restrict__ Ch, __nv_bfloat16* __restrict__ Cl,
      int lda, int ldb, int ldc,
      long long sAo, long long sAi, long long sBo, long long sBi,
      long long sCo, long long sCi, int zInner,
      const float* __restrict__ bias1, const float* __restrict__ bias2,
      long long sB2o, long long sB2i, float alpha, int K)
{
    extern __shared__ char smem[];
    constexpr int BM = 128, BK = 32;
    constexpr int PA   = (TA == 0) ? 80 : 272;
    constexpr int A_SZ = (TA == 0) ? BM * 80 : BK * 272;
    constexpr int PB   = (TB == 1) ? 80 : (BN * 2 + 16);
    constexpr int B_SZ = (TB == 1) ? BN * 80 : BK * PB;
    constexpr int STAGE = 2 * A_SZ + 2 * B_SZ;
    constexpr int MI = (BN == 128) ? 4 : 2;
    constexpr int NI = 4;
    constexpr int WM = (BN == 128) ? 2 : 4;

    const int tid = threadIdx.x;
    const int lane = tid & 31, wid = tid >> 5;
    const int m_base = (wid % WM) * MI * 16;
    const int n_base = (wid / WM) * NI * 8;

    int z = blockIdx.z, zo = z / zInner, zi = z % zInner;
    Ah_ += zo * sAo + zi * sAi;  Al_ += zo * sAo + zi * sAi;
    Bh_ += zo * sBo + zi * sBi;  Bl_ += zo * sBo + zi * sBi;
    const long long coff = zo * sCo + zi * sCi;
    if (OUT == 0) Cf += coff; else { Ch += coff; Cl += coff; }
    const float* b2 = (BIAS == 3) ? (bias2 + zo * sB2o + zi * sB2i) : nullptr;

    const int m0 = blockIdx.y * BM;
    const int n0 = blockIdx.x * BN;

    const uint32_t sb0 = smem_u32(smem);

    // ---- cp.async one chunk into stage buffer ----
    auto stage_in = [&](int c, uint32_t base) {
        const int k0 = c * BK;
        if (TA == 0) {
#pragma unroll
            for (int it = 0; it < (BM * 4) / 256; ++it) {
                int idx = tid + it * 256, r = idx >> 2, sg = idx & 3;
                uint32_t d = base + r * 80 + sg * 16;
                long long o = (long long)(m0 + r) * lda + k0 + sg * 8;
                CP16(d, Ah_ + o);
                CP16(d + A_SZ, Al_ + o);
            }
        } else {
#pragma unroll
            for (int it = 0; it < (BK * 16) / 256; ++it) {
                int idx = tid + it * 256, kr = idx >> 4, sg = idx & 15;
                uint32_t d = base + kr * 272 + sg * 16;
                long long o = (long long)(k0 + kr) * lda + m0 + sg * 8;
                CP16(d, Ah_ + o);
                CP16(d + A_SZ, Al_ + o);
            }
        }
        if (TB == 1) {
#pragma unroll
            for (int it = 0; it < (BN * 4) / 256; ++it) {
                int idx = tid + it * 256, r = idx >> 2, sg = idx & 3;
                uint32_t d = base + 2 * A_SZ + r * 80 + sg * 16;
                long long o = (long long)(n0 + r) * ldb + k0 + sg * 8;
                CP16(d, Bh_ + o);
                CP16(d + B_SZ, Bl_ + o);
            }
        } else {
            constexpr int SEGS = BN / 8;
#pragma unroll
            for (int it = 0; it < (BK * SEGS) / 256; ++it) {
                int idx = tid + it * 256, kr = idx / SEGS, sg = idx % SEGS;
                uint32_t d = base + 2 * A_SZ + kr * PB + sg * 16;
                long long o = (long long)(k0 + kr) * ldb + n0 + sg * 8;
                CP16(d, Bh_ + o);
                CP16(d + B_SZ, Bl_ + o);
            }
        }
    };

    float acc[MI][NI][4] = {};

    const int nch = K / BK;
    stage_in(0, sb0);
    CP_COMMIT();

    for (int c = 0; c < nch; ++c) {
        if (c + 1 < nch) stage_in(c + 1, sb0 + ((c + 1) & 1) * STAGE);
        CP_COMMIT();
        CP_WAIT1();
        __syncthreads();

        const uint32_t ab = sb0 + (c & 1) * STAGE;
        const uint32_t bb = ab + 2 * A_SZ;
#pragma unroll
        for (int ks = 0; ks < 2; ++ks) {
            const int kk = ks * 16;
            uint32_t bh[NI][2], bl[NI][2];
#pragma unroll
            for (int ni = 0; ni < NI; ++ni) {
                uint32_t addr;
                if (TB == 1) {
                    addr = bb + (n_base + ni * 8 + (lane & 7)) * 80 + (kk + ((lane >> 3) & 1) * 8) * 2;
                    ldsm_x2(bh[ni], addr);
                    ldsm_x2(bl[ni], addr + B_SZ);
                } else {
                    addr = bb + (kk + (lane & 15)) * PB + (n_base + ni * 8) * 2;
                    ldsm_x2_t(bh[ni], addr);
                    ldsm_x2_t(bl[ni], addr + B_SZ);
                }
            }
#pragma unroll
            for (int mi = 0; mi < MI; ++mi) {
                uint32_t ah[4], al[4], ad;
                if (TA == 0) {
                    ad = ab + (m_base + mi * 16 + (lane & 15)) * 80 + (kk + (lane >> 4) * 8) * 2;
                    ldsm_x4(ah, ad);
                    ldsm_x4(al, ad + A_SZ);
                } else {
                    ad = ab + (kk + (lane & 7) + (lane >> 4) * 8) * 272
                            + (m_base + mi * 16 + ((lane >> 3) & 1) * 8) * 2;
                    ldsm_x4_t(ah, ad);
                    ldsm_x4_t(al, ad + A_SZ);
                }
#pragma unroll
                for (int ni = 0; ni < NI; ++ni) {
                    mma16816(acc[mi][ni], ah, bh[ni]);
                    mma16816(acc[mi][ni], ah, bl[ni]);
                    mma16816(acc[mi][ni], al, bh[ni]);
                }
            }
        }
        __syncthreads();
    }

    // ---- epilogue ----
#pragma unroll
    for (int mi = 0; mi < MI; ++mi) {
#pragma unroll
        for (int ni = 0; ni < NI; ++ni) {
            int m = m0 + m_base + mi * 16 + (lane >> 2);
            int n = n0 + n_base + ni * 8 + 2 * (lane & 3);
            float v0 = acc[mi][ni][0] * alpha, v1 = acc[mi][ni][1] * alpha;
            float v2 = acc[mi][ni][2] * alpha, v3 = acc[mi][ni][3] * alpha;
            if (BIAS == 1) { float b = bias1[m], bb8 = bias1[m + 8]; v0 += b; v1 += b; v2 += bb8; v3 += bb8; }
            if (BIAS == 2) { float b = bias1[n], bb1 = bias1[n + 1]; v0 += b; v1 += bb1; v2 += b; v3 += bb1; }
            if (BIAS == 3) {
                float c0 = b2[n], c1 = b2[n + 1];
                float bm = bias1[m], bm8 = bias1[m + 8];
                v0 += bm * c0; v1 += bm * c1; v2 += bm8 * c0; v3 += bm8 * c1;
            }
            if (OUT == 0) {
                *reinterpret_cast<float2*>(&Cf[(long long)m * ldc + n]) = make_float2(v0, v1);
                *reinterpret_cast<float2*>(&Cf[(long long)(m + 8) * ldc + n]) = make_float2(v2, v3);
            } else {
                uint32_t h, l;
                split2(v0, v1, h, l);
                *reinterpret_cast<uint32_t*>(&Ch[(long long)m * ldc + n]) = h;
                *reinterpret_cast<uint32_t*>(&Cl[(long long)m * ldc + n]) = l;
                split2(v2, v3, h, l);
                *reinterpret_cast<uint32_t*>(&Ch[(long long)(m + 8) * ldc + n]) = h;
                *reinterpret_cast<uint32_t*>(&Cl[(long long)(m + 8) * ldc + n]) = l;
            }
        }
    }
}

// ---------------------------------------------------------------------------
// Fast exp via FMA polynomial
// ---------------------------------------------------------------------------
__device__ __forceinline__ float fexp(float x)
{
    float t = x * 1.4426950408889634f;
    float k = rintf(t);
    float f = (t - k) * 0.6931471805599453f;
    float p = 1.0f + f * (1.0f + f * (0.5f + f * (0.166666667f +
                     f * (0.0416666668f + f * 0.00833333340f))));
    return __int_as_float(((int)k + 127) << 23) * p;
}

// Row softmax: fp32 scores in, bf16 hi/lo probs out. One block per row.
__global__ void softmax_rows(const float* __restrict__ a,
                             __nv_bfloat16* __restrict__ ph,
                             __nv_bfloat16* __restrict__ pl)
{
    const float* p = a + (long long)blockIdx.x * SEQ;
    int t = threadIdx.x;
    int w = t >> 5, lane = t & 31;

    float2 v[4];
    float m = -1e30f;
#pragma unroll
    for (int i = 0; i < 4; i++) {
        v[i] = reinterpret_cast<const float2*>(p)[t + i * 256];
        m = fmaxf(m, fmaxf(v[i].x, v[i].y));
    }
#pragma unroll
    for (int o = 16; o; o >>= 1) m = fmaxf(m, __shfl_xor_sync(0xffffffffu, m, o));

    __shared__ float red[8];
    if (lane == 0) red[w] = m;
    __syncthreads();
    float bm = red[0];
#pragma unroll
    for (int i = 1; i < 8; i++) bm = fmaxf(bm, red[i]);
    __syncthreads();

    float s = 0.f;
#pragma unroll
    for (int i = 0; i < 4; i++) {
        v[i].x = fexp(v[i].x - bm);
        v[i].y = fexp(v[i].y - bm);
        s += v[i].x + v[i].y;
    }
#pragma unroll
    for (int o = 16; o; o >>= 1) s += __shfl_xor_sync(0xffffffffu, s, o);
    if (lane == 0) red[w] = s;
    __syncthreads();
    float bs = red[0];
#pragma unroll
    for (int i = 1; i < 8; i++) bs += red[i];

    float inv = 1.0f / bs;
    uint32_t* hp = reinterpret_cast<uint32_t*>(ph) + (long long)blockIdx.x * (SEQ / 2);
    uint32_t* lp = reinterpret_cast<uint32_t*>(pl) + (long long)blockIdx.x * (SEQ / 2);
#pragma unroll
    for (int i = 0; i < 4; i++) {
        uint32_t h, l;
        split2(v[i].x * inv, v[i].y * inv, h, l);
        hp[t + i * 256] = h;
        lp[t + i * 256] = l;
    }
}

// S[b*CDIM + c] = sum_t v[b, t, c]  (v reconstructed from hi+lo)
__global__ void colsum_v(const __nv_bfloat16* __restrict__ vh,
                         const __nv_bfloat16* __restrict__ vl,
                         float* __restrict__ s)
{
    int idx = blockIdx.x * blockDim.x + threadIdx.x;
    if (idx >= NB_ * CDIM) return;
    int b = idx >> 10, c = idx & (CDIM - 1);
    long long base = (long long)b * SEQ * CDIM + c;
    float acc = 0.f;
#pragma unroll 8
    for (int t = 0; t < SEQ; t++) {
        long long o = base + (long long)t * CDIM;
        acc += __bfloat162float(vh[o]) + __bfloat162float(vl[o]);
    }
    s[idx] = acc;
}

// ---------------------------------------------------------------------------
// Launch
// ---------------------------------------------------------------------------
extern "C" void kernel_launch(void* const* d_in, const int* in_sizes, int n_in,
                              void* d_out, int out_size)
{
    const float* x      = (const float*)d_in[0];
    const float* w_hseq = (const float*)d_in[1];
    const float* b_hseq = (const float*)d_in[2];
    const float* wq     = (const float*)d_in[3];
    const float* bq     = (const float*)d_in[4];
    const float* wk     = (const float*)d_in[5];
    const float* bk     = (const float*)d_in[6];
    const float* wv     = (const float*)d_in[7];
    const float* bv     = (const float*)d_in[8];
    const float* w_oseq = (const float*)d_in[9];
    const float* b_oseq = (const float*)d_in[10];
    float* out = (float*)d_out;

    __nv_bfloat16 *xbh, *xbl, *whh, *whl, *wqh, *wql, *wkh, *wkl, *wvh, *wvl, *woh, *wol;
    __nv_bfloat16 *xhh, *xhl, *qh, *ql, *kh, *kl, *vh, *vl, *pph, *ppl, *zh, *zl;
    float *attn, *sv;
    cudaGetSymbolAddress((void**)&xbh, g_xb_h);  cudaGetSymbolAddress((void**)&xbl, g_xb_l);
    cudaGetSymbolAddress((void**)&whh, g_whs_h); cudaGetSymbolAddress((void**)&whl, g_whs_l);
    cudaGetSymbolAddress((void**)&wqh, g_wq_h);  cudaGetSymbolAddress((void**)&wql, g_wq_l);
    cudaGetSymbolAddress((void**)&wkh, g_wk_h);  cudaGetSymbolAddress((void**)&wkl, g_wk_l);
    cudaGetSymbolAddress((void**)&wvh, g_wv_h);  cudaGetSymbolAddress((void**)&wvl, g_wv_l);
    cudaGetSymbolAddress((void**)&woh, g_wo_h);  cudaGetSymbolAddress((void**)&wol, g_wo_l);
    cudaGetSymbolAddress((void**)&xhh, g_xh_h);  cudaGetSymbolAddress((void**)&xhl, g_xh_l);
    cudaGetSymbolAddress((void**)&qh,  g_q_h);   cudaGetSymbolAddress((void**)&ql,  g_q_l);
    cudaGetSymbolAddress((void**)&kh,  g_k_h);   cudaGetSymbolAddress((void**)&kl,  g_k_l);
    cudaGetSymbolAddress((void**)&vh,  g_v_h);   cudaGetSymbolAddress((void**)&vl,  g_v_l);
    cudaGetSymbolAddress((void**)&pph, g_p_h);   cudaGetSymbolAddress((void**)&ppl, g_p_l);
    cudaGetSymbolAddress((void**)&zh,  g_z_h);   cudaGetSymbolAddress((void**)&zl,  g_z_l);
    cudaGetSymbolAddress((void**)&attn, g_attn);
    cudaGetSymbolAddress((void**)&sv,   g_s);

    const long long sBT = (long long)SEQ * CDIM;
    const long long sAh_ = (long long)SEQ * SEQ;
    const long long sAb = (long long)NH * SEQ * SEQ;
    const long long sZh_ = (long long)SEQ * HD;
    const long long sZb = (long long)NH * SEQ * HD;

    // ---- convert external fp32 operands to bf16 hi/lo ----
    convert_split<<<(int)(E_X / 4 / 256), 256>>>(x, xbh, xbl, (int)(E_X / 4));
    convert_split<<<(int)(E_WS / 4 / 256), 256>>>(w_hseq, whh, whl, (int)(E_WS / 4));
    convert_split<<<(int)(E_W / 4 / 256), 256>>>(wq, wqh, wql, (int)(E_W / 4));
    convert_split<<<(int)(E_W / 4 / 256), 256>>>(wk, wkh, wkl, (int)(E_W / 4));
    convert_split<<<(int)(E_W / 4 / 256), 256>>>(wv, wvh, wvl, (int)(E_W / 4));
    convert_split<<<(int)(E_WS / 4 / 256), 256>>>(w_oseq, woh, wol, (int)(E_WS / 4));

    // smem sizes: 2 stages of (2*A_SZ + 2*B_SZ)
    const int SM_A = 2 * (2 * 10240 + 2 * 8704);   // 75776  <0,0,1,128,1>
    const int SM_B = 2 * (2 * 10240 + 2 * 10240);  // 81920  <0,1,*,128,*>
    const int SM_E = 2 * (2 * 8704 + 2 * 4608);    // 53248  <1,0,0,64,1>
    const int SM_F = 2 * (2 * 10240 + 2 * 4608);   // 59392  <0,0,3,64,0>

    cudaFuncSetAttribute(tgemm<0, 0, 1, 128, 1>, cudaFuncAttributeMaxDynamicSharedMemorySize, SM_A);
    cudaFuncSetAttribute(tgemm<0, 1, 2, 128, 1>, cudaFuncAttributeMaxDynamicSharedMemorySize, SM_B);
    cudaFuncSetAttribute(tgemm<0, 1, 0, 128, 0>, cudaFuncAttributeMaxDynamicSharedMemorySize, SM_B);
    cudaFuncSetAttribute(tgemm<1, 0, 0, 64, 1>,  cudaFuncAttributeMaxDynamicSharedMemorySize, SM_E);
    cudaFuncSetAttribute(tgemm<0, 0, 3, 64, 0>,  cudaFuncAttributeMaxDynamicSharedMemorySize, SM_F);

    // Stage A: xh[b,t,c] = sum_s w_hseq[t,s]*x[b,s,c] + b_hseq[t]  -> bf16 pair
    tgemm<0, 0, 1, 128, 1><<<dim3(CDIM / 128, SEQ / 128, NB_), 256, SM_A>>>(
        whh, whl, xbh, xbl, nullptr, xhh, xhl,
        SEQ, CDIM, CDIM, 0, 0, sBT, 0, sBT, 0, 1,
        b_hseq, nullptr, 0, 0, 1.0f, SEQ);

    // Stage B: q/k/v[b,t,o] = xh @ W^T + bias  -> bf16 pairs
    tgemm<0, 1, 2, 128, 1><<<dim3(CDIM / 128, (NB_ * SEQ) / 128, 1), 256, SM_B>>>(
        xhh, xhl, wqh, wql, nullptr, qh, ql,
        CDIM, CDIM, CDIM, 0, 0, 0, 0, 0, 0, 1,
        bq, nullptr, 0, 0, 1.0f, CDIM);
    tgemm<0, 1, 2, 128, 1><<<dim3(CDIM / 128, (NB_ * SEQ) / 128, 1), 256, SM_B>>>(
        xhh, xhl, wkh, wkl, nullptr, kh, kl,
        CDIM, CDIM, CDIM, 0, 0, 0, 0, 0, 0, 1,
        bk, nullptr, 0, 0, 1.0f, CDIM);
    tgemm<0, 1, 2, 128, 1><<<dim3(CDIM / 128, (NB_ * SEQ) / 128, 1), 256, SM_B>>>(
        xhh, xhl, wvh, wvl, nullptr, vh, vl,
        CDIM, CDIM, CDIM, 0, 0, 0, 0, 0, 0, 1,
        bv, nullptr, 0, 0, 1.0f, CDIM);

    // Stage C: scores[b,h,qi,kj] = (1/8) q.k  -> fp32
    tgemm<0, 1, 0, 128, 0><<<dim3(SEQ / 128, SEQ / 128, NB_ * NH), 256, SM_B>>>(
        qh, ql, kh, kl, attn, nullptr, nullptr,
        CDIM, CDIM, SEQ, sBT, HD, sBT, HD, sAb, sAh_, NH,
        nullptr, nullptr, 0, 0, 0.125f, HD);

    // Stage D: softmax -> bf16 pair probs
    softmax_rows<<<NB_ * NH * SEQ, 256>>>(attn, pph, ppl);

    // Column sums of v (rank-1 bias term)
    colsum_v<<<(NB_ * CDIM + 255) / 256, 256>>>(vh, vl, sv);

    // Stage E: Z[b,h,kj,d] = sum_q p[q,kj]*v[q,h*64+d]  -> bf16 pair
    tgemm<1, 0, 0, 64, 1><<<dim3(1, SEQ / 128, NB_ * NH), 256, SM_E>>>(
        pph, ppl, vh, vl, nullptr, zh, zl,
        SEQ, CDIM, HD, sAb, sAh_, sBT, HD, sZb, sZh_, NH,
        nullptr, nullptr, 0, 0, 1.0f, SEQ);

    // Stage F: out[b,o,h*64+d] = sum_k w_oseq[o,k]*Z[k,d] + b_oseq[o]*S[b,h*64+d]
    tgemm<0, 0, 3, 64, 0><<<dim3(1, SEQ / 128, NB_ * NH), 256, SM_F>>>(
        woh, wol, zh, zl, out, nullptr, nullptr,
        SEQ, HD, CDIM, 0, 0, sZb, sZh_, sBT, HD, NH,
        b_oseq, sv, CDIM, HD, 1.0f, SEQ);
}

// round 6
// speedup vs baseline: 2.5633x; 1.0758x over previous
#include <cuda_runtime.h>
#include <cuda_bf16.h>
#include <cstdint>

// Problem constants
#define NB_   2
#define SEQ  2048
#define CDIM 1024
#define NH   16
#define HD   64

// ---------------------------------------------------------------------------
// Static device scratch
// ---------------------------------------------------------------------------
#define E_X   ((size_t)NB_ * SEQ * CDIM)      // 4M elems
#define E_WS  ((size_t)SEQ * SEQ)             // 4M
#define E_W   ((size_t)CDIM * CDIM)           // 1M
#define E_P   ((size_t)NB_ * NH * SEQ * SEQ)  // 134M
#define E_Z   ((size_t)NB_ * NH * SEQ * HD)   // 4M

__device__ __nv_bfloat16 g_xb_h[E_X],  g_xb_l[E_X];
__device__ __nv_bfloat16 g_whs_h[E_WS], g_whs_l[E_WS];
__device__ __nv_bfloat16 g_wq_h[E_W],  g_wq_l[E_W];
__device__ __nv_bfloat16 g_wk_h[E_W],  g_wk_l[E_W];
__device__ __nv_bfloat16 g_wv_h[E_W],  g_wv_l[E_W];
__device__ __nv_bfloat16 g_wo_h[E_WS], g_wo_l[E_WS];
__device__ __nv_bfloat16 g_xh_h[E_X],  g_xh_l[E_X];
__device__ __nv_bfloat16 g_q_h[E_X],   g_q_l[E_X];
__device__ __nv_bfloat16 g_k_h[E_X],   g_k_l[E_X];
__device__ __nv_bfloat16 g_v_h[E_X],   g_v_l[E_X];
__device__ __nv_bfloat16 g_attn[E_P];               // bf16 scores (256 MB)
__device__ __nv_bfloat16 g_p_h[E_P];                // bf16 probs (256 MB)
__device__ __nv_bfloat16 g_z_h[E_Z],   g_z_l[E_Z];
__device__ float         g_s[(size_t)NB_ * CDIM];   // colsum of v

// ---------------------------------------------------------------------------
// Primitives
// ---------------------------------------------------------------------------
__device__ __forceinline__ uint32_t smem_u32(const void* p) {
    uint32_t a;
    asm("{ .reg .u64 t; cvta.to.shared.u64 t, %1; cvt.u32.u64 %0, t; }" : "=r"(a) : "l"(p));
    return a;
}
#define CP16(d, s) asm volatile("cp.async.cg.shared.global [%0], [%1], 16;" :: "r"(d), "l"(s))
#define CP_COMMIT() asm volatile("cp.async.commit_group;" ::: "memory")
#define CP_WAIT1()  asm volatile("cp.async.wait_group 1;" ::: "memory")

__device__ __forceinline__ void ldsm_x4(uint32_t (&r)[4], uint32_t addr) {
    asm volatile("ldmatrix.sync.aligned.m8n8.x4.shared.b16 {%0,%1,%2,%3}, [%4];"
                 : "=r"(r[0]), "=r"(r[1]), "=r"(r[2]), "=r"(r[3]) : "r"(addr));
}
__device__ __forceinline__ void ldsm_x4_t(uint32_t (&r)[4], uint32_t addr) {
    asm volatile("ldmatrix.sync.aligned.m8n8.x4.trans.shared.b16 {%0,%1,%2,%3}, [%4];"
                 : "=r"(r[0]), "=r"(r[1]), "=r"(r[2]), "=r"(r[3]) : "r"(addr));
}
__device__ __forceinline__ void ldsm_x2(uint32_t (&r)[2], uint32_t addr) {
    asm volatile("ldmatrix.sync.aligned.m8n8.x2.shared.b16 {%0,%1}, [%2];"
                 : "=r"(r[0]), "=r"(r[1]) : "r"(addr));
}
__device__ __forceinline__ void ldsm_x2_t(uint32_t (&r)[2], uint32_t addr) {
    asm volatile("ldmatrix.sync.aligned.m8n8.x2.trans.shared.b16 {%0,%1}, [%2];"
                 : "=r"(r[0]), "=r"(r[1]) : "r"(addr));
}
__device__ __forceinline__ void mma16816(float (&c)[4], const uint32_t (&a)[4],
                                         const uint32_t (&b)[2]) {
    asm volatile(
        "mma.sync.aligned.m16n8k16.row.col.f32.bf16.bf16.f32 "
        "{%0,%1,%2,%3}, {%4,%5,%6,%7}, {%8,%9}, {%0,%1,%2,%3};"
        : "+f"(c[0]), "+f"(c[1]), "+f"(c[2]), "+f"(c[3])
        : "r"(a[0]), "r"(a[1]), "r"(a[2]), "r"(a[3]), "r"(b[0]), "r"(b[1]));
}

// fp32 -> (bf16 hi, bf16 lo) split, two elements at a time
__device__ __forceinline__ void split2(float x0, float x1, uint32_t& hi2, uint32_t& lo2)
{
    asm("cvt.rn.bf16x2.f32 %0, %1, %2;" : "=r"(hi2) : "f"(x1), "f"(x0));
    float h0 = __uint_as_float(hi2 << 16);
    float h1 = __uint_as_float(hi2 & 0xffff0000u);
    asm("cvt.rn.bf16x2.f32 %0, %1, %2;" : "=r"(lo2) : "f"(x1 - h1), "f"(x0 - h0));
}
__device__ __forceinline__ uint32_t pack_bf2(float x0, float x1)
{
    uint32_t r;
    asm("cvt.rn.bf16x2.f32 %0, %1, %2;" : "=r"(r) : "f"(x1), "f"(x0));
    return r;
}

// ---------------------------------------------------------------------------
// fp32 -> bf16 hi/lo conversion (inputs & weights)
// ---------------------------------------------------------------------------
__global__ void convert_split(const float* __restrict__ src,
                              __nv_bfloat16* __restrict__ hi,
                              __nv_bfloat16* __restrict__ lo, int n4)
{
    int i = blockIdx.x * blockDim.x + threadIdx.x;
    if (i >= n4) return;
    float4 v = reinterpret_cast<const float4*>(src)[i];
    uint32_t h0, l0, h1, l1;
    split2(v.x, v.y, h0, l0);
    split2(v.z, v.w, h1, l1);
    reinterpret_cast<uint2*>(hi)[i] = make_uint2(h0, h1);
    reinterpret_cast<uint2*>(lo)[i] = make_uint2(l0, l1);
}

// ---------------------------------------------------------------------------
// Tensor-core bf16x3 GEMM.
//   C[m,n] = alpha * sum_k A[m,k]*B[n,k]  (+ bias), fp32 accumulate.
//   TA=0: A gmem [m,k].  TA=1: A gmem [k,m].
//   TB=1: B gmem [n,k].  TB=0: B gmem [k,n].
//   OUT=0: fp32 C.  OUT=1: bf16 hi/lo pair C.  OUT=2: bf16 hi-only C.
//   AP=1: A is hi/lo pair (3 MMA passes).  AP=0: A single bf16 (2 passes).
// ---------------------------------------------------------------------------
template <int TA, int TB, int BIAS, int BN, int OUT, int AP>
__global__ void __launch_bounds__(256, 2)
tgemm(const __nv_bfloat16* __restrict__ Ah_, const __nv_bfloat16* __restrict__ Al_,
      const __nv_bfloat16* __restrict__ Bh_, const __nv_bfloat16* __restrict__ Bl_,
      float* __restrict__ Cf,
      __nv_bfloat16* __restrict__ Ch, __nv_bfloat16* __restrict__ Cl,
      int lda, int ldb, int ldc,
      long long sAo, long long sAi, long long sBo, long long sBi,
      long long sCo, long long sCi, int zInner,
      const float* __restrict__ bias1, const float* __restrict__ bias2,
      long long sB2o, long long sB2i, float alpha, int K)
{
    extern __shared__ char smem[];
    constexpr int BM = 128, BK = 32;
    constexpr int A_SZ = (TA == 0) ? BM * 80 : BK * 272;
    constexpr int A_TOT = (AP ? 2 : 1) * A_SZ;
    constexpr int PB   = (TB == 1) ? 80 : (BN * 2 + 16);
    constexpr int B_SZ = (TB == 1) ? BN * 80 : BK * PB;
    constexpr int STAGE = A_TOT + 2 * B_SZ;
    constexpr int MI = (BN == 128) ? 4 : 2;
    constexpr int NI = 4;
    constexpr int WM = (BN == 128) ? 2 : 4;

    const int tid = threadIdx.x;
    const int lane = tid & 31, wid = tid >> 5;
    const int m_base = (wid % WM) * MI * 16;
    const int n_base = (wid / WM) * NI * 8;

    int z = blockIdx.z, zo = z / zInner, zi = z % zInner;
    Ah_ += zo * sAo + zi * sAi;
    if (AP) Al_ += zo * sAo + zi * sAi;
    Bh_ += zo * sBo + zi * sBi;  Bl_ += zo * sBo + zi * sBi;
    const long long coff = zo * sCo + zi * sCi;
    if (OUT == 0) Cf += coff; else { Ch += coff; if (OUT == 1) Cl += coff; }
    const float* b2 = (BIAS == 3) ? (bias2 + zo * sB2o + zi * sB2i) : nullptr;

    const int m0 = blockIdx.y * BM;
    const int n0 = blockIdx.x * BN;

    const uint32_t sb0 = smem_u32(smem);

    auto stage_in = [&](int c, uint32_t base) {
        const int k0 = c * BK;
        if (TA == 0) {
#pragma unroll
            for (int it = 0; it < (BM * 4) / 256; ++it) {
                int idx = tid + it * 256, r = idx >> 2, sg = idx & 3;
                uint32_t d = base + r * 80 + sg * 16;
                long long o = (long long)(m0 + r) * lda + k0 + sg * 8;
                CP16(d, Ah_ + o);
                if (AP) CP16(d + A_SZ, Al_ + o);
            }
        } else {
#pragma unroll
            for (int it = 0; it < (BK * 16) / 256; ++it) {
                int idx = tid + it * 256, kr = idx >> 4, sg = idx & 15;
                uint32_t d = base + kr * 272 + sg * 16;
                long long o = (long long)(k0 + kr) * lda + m0 + sg * 8;
                CP16(d, Ah_ + o);
                if (AP) CP16(d + A_SZ, Al_ + o);
            }
        }
        if (TB == 1) {
#pragma unroll
            for (int it = 0; it < (BN * 4) / 256; ++it) {
                int idx = tid + it * 256, r = idx >> 2, sg = idx & 3;
                uint32_t d = base + A_TOT + r * 80 + sg * 16;
                long long o = (long long)(n0 + r) * ldb + k0 + sg * 8;
                CP16(d, Bh_ + o);
                CP16(d + B_SZ, Bl_ + o);
            }
        } else {
            constexpr int SEGS = BN / 8;
#pragma unroll
            for (int it = 0; it < (BK * SEGS) / 256; ++it) {
                int idx = tid + it * 256, kr = idx / SEGS, sg = idx % SEGS;
                uint32_t d = base + A_TOT + kr * PB + sg * 16;
                long long o = (long long)(k0 + kr) * ldb + n0 + sg * 8;
                CP16(d, Bh_ + o);
                CP16(d + B_SZ, Bl_ + o);
            }
        }
    };

    float acc[MI][NI][4] = {};

    const int nch = K / BK;
    stage_in(0, sb0);
    CP_COMMIT();

    for (int c = 0; c < nch; ++c) {
        if (c + 1 < nch) stage_in(c + 1, sb0 + ((c + 1) & 1) * STAGE);
        CP_COMMIT();
        CP_WAIT1();
        __syncthreads();

        const uint32_t ab = sb0 + (c & 1) * STAGE;
        const uint32_t bb = ab + A_TOT;
#pragma unroll
        for (int ks = 0; ks < 2; ++ks) {
            const int kk = ks * 16;
            uint32_t bh[NI][2], bl[NI][2];
#pragma unroll
            for (int ni = 0; ni < NI; ++ni) {
                uint32_t addr;
                if (TB == 1) {
                    addr = bb + (n_base + ni * 8 + (lane & 7)) * 80 + (kk + ((lane >> 3) & 1) * 8) * 2;
                    ldsm_x2(bh[ni], addr);
                    ldsm_x2(bl[ni], addr + B_SZ);
                } else {
                    addr = bb + (kk + (lane & 15)) * PB + (n_base + ni * 8) * 2;
                    ldsm_x2_t(bh[ni], addr);
                    ldsm_x2_t(bl[ni], addr + B_SZ);
                }
            }
#pragma unroll
            for (int mi = 0; mi < MI; ++mi) {
                uint32_t ah[4], al[4], ad;
                if (TA == 0) {
                    ad = ab + (m_base + mi * 16 + (lane & 15)) * 80 + (kk + (lane >> 4) * 8) * 2;
                    ldsm_x4(ah, ad);
                    if (AP) ldsm_x4(al, ad + A_SZ);
                } else {
                    ad = ab + (kk + (lane & 7) + (lane >> 4) * 8) * 272
                            + (m_base + mi * 16 + ((lane >> 3) & 1) * 8) * 2;
                    ldsm_x4_t(ah, ad);
                    if (AP) ldsm_x4_t(al, ad + A_SZ);
                }
#pragma unroll
                for (int ni = 0; ni < NI; ++ni) {
                    mma16816(acc[mi][ni], ah, bh[ni]);
                    mma16816(acc[mi][ni], ah, bl[ni]);
                    if (AP) mma16816(acc[mi][ni], al, bh[ni]);
                }
            }
        }
        __syncthreads();
    }

    // ---- epilogue ----
#pragma unroll
    for (int mi = 0; mi < MI; ++mi) {
#pragma unroll
        for (int ni = 0; ni < NI; ++ni) {
            int m = m0 + m_base + mi * 16 + (lane >> 2);
            int n = n0 + n_base + ni * 8 + 2 * (lane & 3);
            float v0 = acc[mi][ni][0] * alpha, v1 = acc[mi][ni][1] * alpha;
            float v2 = acc[mi][ni][2] * alpha, v3 = acc[mi][ni][3] * alpha;
            if (BIAS == 1) { float b = bias1[m], bb8 = bias1[m + 8]; v0 += b; v1 += b; v2 += bb8; v3 += bb8; }
            if (BIAS == 2) { float b = bias1[n], bb1 = bias1[n + 1]; v0 += b; v1 += bb1; v2 += b; v3 += bb1; }
            if (BIAS == 3) {
                float c0 = b2[n], c1 = b2[n + 1];
                float bm = bias1[m], bm8 = bias1[m + 8];
                v0 += bm * c0; v1 += bm * c1; v2 += bm8 * c0; v3 += bm8 * c1;
            }
            if (OUT == 0) {
                *reinterpret_cast<float2*>(&Cf[(long long)m * ldc + n]) = make_float2(v0, v1);
                *reinterpret_cast<float2*>(&Cf[(long long)(m + 8) * ldc + n]) = make_float2(v2, v3);
            } else if (OUT == 1) {
                uint32_t h, l;
                split2(v0, v1, h, l);
                *reinterpret_cast<uint32_t*>(&Ch[(long long)m * ldc + n]) = h;
                *reinterpret_cast<uint32_t*>(&Cl[(long long)m * ldc + n]) = l;
                split2(v2, v3, h, l);
                *reinterpret_cast<uint32_t*>(&Ch[(long long)(m + 8) * ldc + n]) = h;
                *reinterpret_cast<uint32_t*>(&Cl[(long long)(m + 8) * ldc + n]) = l;
            } else {
                *reinterpret_cast<uint32_t*>(&Ch[(long long)m * ldc + n]) = pack_bf2(v0, v1);
                *reinterpret_cast<uint32_t*>(&Ch[(long long)(m + 8) * ldc + n]) = pack_bf2(v2, v3);
            }
        }
    }
}

// ---------------------------------------------------------------------------
// Fast exp via FMA polynomial
// ---------------------------------------------------------------------------
__device__ __forceinline__ float fexp(float x)
{
    float t = x * 1.4426950408889634f;
    float k = rintf(t);
    float f = (t - k) * 0.6931471805599453f;
    float p = 1.0f + f * (1.0f + f * (0.5f + f * (0.166666667f +
                     f * (0.0416666668f + f * 0.00833333340f))));
    return __int_as_float(((int)k + 127) << 23) * p;
}

// Row softmax: bf16 scores in, bf16 probs out (hi only). One block per row.
__global__ void softmax_rows(const __nv_bfloat16* __restrict__ a,
                             __nv_bfloat16* __restrict__ ph)
{
    const uint32_t* p32 = reinterpret_cast<const uint32_t*>(a) + (long long)blockIdx.x * (SEQ / 2);
    int t = threadIdx.x;
    int w = t >> 5, lane = t & 31;

    float2 v[4];
    float m = -1e30f;
#pragma unroll
    for (int i = 0; i < 4; i++) {
        uint32_t u = p32[t + i * 256];
        v[i] = __bfloat1622float2(*reinterpret_cast<__nv_bfloat162*>(&u));
        m = fmaxf(m, fmaxf(v[i].x, v[i].y));
    }
#pragma unroll
    for (int o = 16; o; o >>= 1) m = fmaxf(m, __shfl_xor_sync(0xffffffffu, m, o));

    __shared__ float red[8];
    if (lane == 0) red[w] = m;
    __syncthreads();
    float bm = red[0];
#pragma unroll
    for (int i = 1; i < 8; i++) bm = fmaxf(bm, red[i]);
    __syncthreads();

    float s = 0.f;
#pragma unroll
    for (int i = 0; i < 4; i++) {
        v[i].x = fexp(v[i].x - bm);
        v[i].y = fexp(v[i].y - bm);
        s += v[i].x + v[i].y;
    }
#pragma unroll
    for (int o = 16; o; o >>= 1) s += __shfl_xor_sync(0xffffffffu, s, o);
    if (lane == 0) red[w] = s;
    __syncthreads();
    float bs = red[0];
#pragma unroll
    for (int i = 1; i < 8; i++) bs += red[i];

    float inv = 1.0f / bs;
    uint32_t* hp = reinterpret_cast<uint32_t*>(ph) + (long long)blockIdx.x * (SEQ / 2);
#pragma unroll
    for (int i = 0; i < 4; i++)
        hp[t + i * 256] = pack_bf2(v[i].x * inv, v[i].y * inv);
}

// S[b*CDIM + c] = sum_t v[b, t, c]
__global__ void colsum_v(const __nv_bfloat16* __restrict__ vh,
                         const __nv_bfloat16* __restrict__ vl,
                         float* __restrict__ s)
{
    int idx = blockIdx.x * blockDim.x + threadIdx.x;
    if (idx >= NB_ * CDIM) return;
    int b = idx >> 10, c = idx & (CDIM - 1);
    long long base = (long long)b * SEQ * CDIM + c;
    float acc = 0.f;
#pragma unroll 8
    for (int t = 0; t < SEQ; t++) {
        long long o = base + (long long)t * CDIM;
        acc += __bfloat162float(vh[o]) + __bfloat162float(vl[o]);
    }
    s[idx] = acc;
}

// ---------------------------------------------------------------------------
// Launch
// ---------------------------------------------------------------------------
extern "C" void kernel_launch(void* const* d_in, const int* in_sizes, int n_in,
                              void* d_out, int out_size)
{
    const float* x      = (const float*)d_in[0];
    const float* w_hseq = (const float*)d_in[1];
    const float* b_hseq = (const float*)d_in[2];
    const float* wq     = (const float*)d_in[3];
    const float* bq     = (const float*)d_in[4];
    const float* wk     = (const float*)d_in[5];
    const float* bk     = (const float*)d_in[6];
    const float* wv     = (const float*)d_in[7];
    const float* bv     = (const float*)d_in[8];
    const float* w_oseq = (const float*)d_in[9];
    const float* b_oseq = (const float*)d_in[10];
    float* out = (float*)d_out;

    __nv_bfloat16 *xbh, *xbl, *whh, *whl, *wqh, *wql, *wkh, *wkl, *wvh, *wvl, *woh, *wol;
    __nv_bfloat16 *xhh, *xhl, *qh, *ql, *kh, *kl, *vh, *vl, *pph, *zh, *zl, *attn;
    float *sv;
    cudaGetSymbolAddress((void**)&xbh, g_xb_h);  cudaGetSymbolAddress((void**)&xbl, g_xb_l);
    cudaGetSymbolAddress((void**)&whh, g_whs_h); cudaGetSymbolAddress((void**)&whl, g_whs_l);
    cudaGetSymbolAddress((void**)&wqh, g_wq_h);  cudaGetSymbolAddress((void**)&wql, g_wq_l);
    cudaGetSymbolAddress((void**)&wkh, g_wk_h);  cudaGetSymbolAddress((void**)&wkl, g_wk_l);
    cudaGetSymbolAddress((void**)&wvh, g_wv_h);  cudaGetSymbolAddress((void**)&wvl, g_wv_l);
    cudaGetSymbolAddress((void**)&woh, g_wo_h);  cudaGetSymbolAddress((void**)&wol, g_wo_l);
    cudaGetSymbolAddress((void**)&xhh, g_xh_h);  cudaGetSymbolAddress((void**)&xhl, g_xh_l);
    cudaGetSymbolAddress((void**)&qh,  g_q_h);   cudaGetSymbolAddress((void**)&ql,  g_q_l);
    cudaGetSymbolAddress((void**)&kh,  g_k_h);   cudaGetSymbolAddress((void**)&kl,  g_k_l);
    cudaGetSymbolAddress((void**)&vh,  g_v_h);   cudaGetSymbolAddress((void**)&vl,  g_v_l);
    cudaGetSymbolAddress((void**)&pph, g_p_h);
    cudaGetSymbolAddress((void**)&zh,  g_z_h);   cudaGetSymbolAddress((void**)&zl,  g_z_l);
    cudaGetSymbolAddress((void**)&attn, g_attn);
    cudaGetSymbolAddress((void**)&sv,   g_s);

    const long long sBT = (long long)SEQ * CDIM;
    const long long sAh_ = (long long)SEQ * SEQ;
    const long long sAb = (long long)NH * SEQ * SEQ;
    const long long sZh_ = (long long)SEQ * HD;
    const long long sZb = (long long)NH * SEQ * HD;

    convert_split<<<(int)(E_X / 4 / 256), 256>>>(x, xbh, xbl, (int)(E_X / 4));
    convert_split<<<(int)(E_WS / 4 / 256), 256>>>(w_hseq, whh, whl, (int)(E_WS / 4));
    convert_split<<<(int)(E_W / 4 / 256), 256>>>(wq, wqh, wql, (int)(E_W / 4));
    convert_split<<<(int)(E_W / 4 / 256), 256>>>(wk, wkh, wkl, (int)(E_W / 4));
    convert_split<<<(int)(E_W / 4 / 256), 256>>>(wv, wvh, wvl, (int)(E_W / 4));
    convert_split<<<(int)(E_WS / 4 / 256), 256>>>(w_oseq, woh, wol, (int)(E_WS / 4));

    // smem: 2 stages of (A_TOT + 2*B_SZ)
    const int SM_A = 2 * (2 * 10240 + 2 * 8704);   // 75776  <0,0,1,128,1,1>
    const int SM_B = 2 * (2 * 10240 + 2 * 10240);  // 81920  <0,1,*,128,*,1>
    const int SM_E = 2 * (8704 + 2 * 4608);        // 35840  <1,0,0,64,1,0>
    const int SM_F = 2 * (2 * 10240 + 2 * 4608);   // 59392  <0,0,3,64,0,1>

    cudaFuncSetAttribute(tgemm<0, 0, 1, 128, 1, 1>, cudaFuncAttributeMaxDynamicSharedMemorySize, SM_A);
    cudaFuncSetAttribute(tgemm<0, 1, 2, 128, 1, 1>, cudaFuncAttributeMaxDynamicSharedMemorySize, SM_B);
    cudaFuncSetAttribute(tgemm<0, 1, 0, 128, 2, 1>, cudaFuncAttributeMaxDynamicSharedMemorySize, SM_B);
    cudaFuncSetAttribute(tgemm<1, 0, 0, 64, 1, 0>,  cudaFuncAttributeMaxDynamicSharedMemorySize, SM_E);
    cudaFuncSetAttribute(tgemm<0, 0, 3, 64, 0, 1>,  cudaFuncAttributeMaxDynamicSharedMemorySize, SM_F);

    // Stage A: xh[b,t,c] = sum_s w_hseq[t,s]*x[b,s,c] + b_hseq[t]  -> bf16 pair
    tgemm<0, 0, 1, 128, 1, 1><<<dim3(CDIM / 128, SEQ / 128, NB_), 256, SM_A>>>(
        whh, whl, xbh, xbl, nullptr, xhh, xhl,
        SEQ, CDIM, CDIM, 0, 0, sBT, 0, sBT, 0, 1,
        b_hseq, nullptr, 0, 0, 1.0f, SEQ);

    // Stage B: q/k/v[b,t,o] = xh @ W^T + bias  -> bf16 pairs
    tgemm<0, 1, 2, 128, 1, 1><<<dim3(CDIM / 128, (NB_ * SEQ) / 128, 1), 256, SM_B>>>(
        xhh, xhl, wqh, wql, nullptr, qh, ql,
        CDIM, CDIM, CDIM, 0, 0, 0, 0, 0, 0, 1,
        bq, nullptr, 0, 0, 1.0f, CDIM);
    tgemm<0, 1, 2, 128, 1, 1><<<dim3(CDIM / 128, (NB_ * SEQ) / 128, 1), 256, SM_B>>>(
        xhh, xhl, wkh, wkl, nullptr, kh, kl,
        CDIM, CDIM, CDIM, 0, 0, 0, 0, 0, 0, 1,
        bk, nullptr, 0, 0, 1.0f, CDIM);
    tgemm<0, 1, 2, 128, 1, 1><<<dim3(CDIM / 128, (NB_ * SEQ) / 128, 1), 256, SM_B>>>(
        xhh, xhl, wvh, wvl, nullptr, vh, vl,
        CDIM, CDIM, CDIM, 0, 0, 0, 0, 0, 0, 1,
        bv, nullptr, 0, 0, 1.0f, CDIM);

    // Stage C: scores = (1/8) q.k  -> bf16 (hi only)
    tgemm<0, 1, 0, 128, 2, 1><<<dim3(SEQ / 128, SEQ / 128, NB_ * NH), 256, SM_B>>>(
        qh, ql, kh, kl, nullptr, attn, nullptr,
        CDIM, CDIM, SEQ, sBT, HD, sBT, HD, sAb, sAh_, NH,
        nullptr, nullptr, 0, 0, 0.125f, HD);

    // Stage D: softmax -> bf16 probs (hi only)
    softmax_rows<<<NB_ * NH * SEQ, 256>>>(attn, pph);

    // Column sums of v (rank-1 bias term)
    colsum_v<<<(NB_ * CDIM + 255) / 256, 256>>>(vh, vl, sv);

    // Stage E: Z[b,h,kj,d] = sum_q p[q,kj]*v[q,h*64+d]  -> bf16 pair (A single)
    tgemm<1, 0, 0, 64, 1, 0><<<dim3(1, SEQ / 128, NB_ * NH), 256, SM_E>>>(
        pph, nullptr, vh, vl, nullptr, zh, zl,
        SEQ, CDIM, HD, sAb, sAh_, sBT, HD, sZb, sZh_, NH,
        nullptr, nullptr, 0, 0, 1.0f, SEQ);

    // Stage F: out = w_oseq @ Z + b_oseq*S
    tgemm<0, 0, 3, 64, 0, 1><<<dim3(1, SEQ / 128, NB_ * NH), 256, SM_F>>>(
        woh, wol, zh, zl, out, nullptr, nullptr,
        SEQ, HD, CDIM, 0, 0, sZb, sZh_, sBT, HD, NH,
        b_oseq, sv, CDIM, HD, 1.0f, SEQ);
}

// round 7
// speedup vs baseline: 2.7105x; 1.0575x over previous
#include <cuda_runtime.h>
#include <cuda_bf16.h>
#include <cstdint>

// Problem constants
#define NB_   2
#define SEQ  2048
#define CDIM 1024
#define NH   16
#define HD   64

// ---------------------------------------------------------------------------
// Static device scratch
// ---------------------------------------------------------------------------
#define E_X   ((size_t)NB_ * SEQ * CDIM)      // 4M elems
#define E_WS  ((size_t)SEQ * SEQ)             // 4M
#define E_W   ((size_t)CDIM * CDIM)           // 1M
#define E_P   ((size_t)NB_ * NH * SEQ * SEQ)  // 134M
#define E_Z   ((size_t)NB_ * NH * SEQ * HD)   // 4M

__device__ __nv_bfloat16 g_xb_h[E_X],  g_xb_l[E_X];
__device__ __nv_bfloat16 g_whs_h[E_WS], g_whs_l[E_WS];
__device__ __nv_bfloat16 g_wq_h[E_W],  g_wq_l[E_W];
__device__ __nv_bfloat16 g_wk_h[E_W],  g_wk_l[E_W];
__device__ __nv_bfloat16 g_wv_h[E_W],  g_wv_l[E_W];
__device__ __nv_bfloat16 g_wo_h[E_WS], g_wo_l[E_WS];
__device__ __nv_bfloat16 g_xh_h[E_X],  g_xh_l[E_X];
__device__ __nv_bfloat16 g_q_h[E_X],   g_q_l[E_X];
__device__ __nv_bfloat16 g_k_h[E_X],   g_k_l[E_X];
__device__ __nv_bfloat16 g_v_h[E_X],   g_v_l[E_X];
__device__ __nv_bfloat16 g_attn[E_P];               // bf16 scores (256 MB)
__device__ __nv_bfloat16 g_p_h[E_P];                // bf16 probs (256 MB)
__device__ __nv_bfloat16 g_z_h[E_Z],   g_z_l[E_Z];
__device__ float         g_s[(size_t)NB_ * CDIM];   // colsum of v

// ---------------------------------------------------------------------------
// Primitives
// ---------------------------------------------------------------------------
__device__ __forceinline__ uint32_t smem_u32(const void* p) {
    uint32_t a;
    asm("{ .reg .u64 t; cvta.to.shared.u64 t, %1; cvt.u32.u64 %0, t; }" : "=r"(a) : "l"(p));
    return a;
}
#define CP16(d, s) asm volatile("cp.async.cg.shared.global [%0], [%1], 16;" :: "r"(d), "l"(s))
#define CP_COMMIT() asm volatile("cp.async.commit_group;" ::: "memory")
#define CP_WAIT1()  asm volatile("cp.async.wait_group 1;" ::: "memory")

__device__ __forceinline__ void ldsm_x4(uint32_t (&r)[4], uint32_t addr) {
    asm volatile("ldmatrix.sync.aligned.m8n8.x4.shared.b16 {%0,%1,%2,%3}, [%4];"
                 : "=r"(r[0]), "=r"(r[1]), "=r"(r[2]), "=r"(r[3]) : "r"(addr));
}
__device__ __forceinline__ void ldsm_x4_t(uint32_t (&r)[4], uint32_t addr) {
    asm volatile("ldmatrix.sync.aligned.m8n8.x4.trans.shared.b16 {%0,%1,%2,%3}, [%4];"
                 : "=r"(r[0]), "=r"(r[1]), "=r"(r[2]), "=r"(r[3]) : "r"(addr));
}
__device__ __forceinline__ void ldsm_x2(uint32_t (&r)[2], uint32_t addr) {
    asm volatile("ldmatrix.sync.aligned.m8n8.x2.shared.b16 {%0,%1}, [%2];"
                 : "=r"(r[0]), "=r"(r[1]) : "r"(addr));
}
__device__ __forceinline__ void ldsm_x2_t(uint32_t (&r)[2], uint32_t addr) {
    asm volatile("ldmatrix.sync.aligned.m8n8.x2.trans.shared.b16 {%0,%1}, [%2];"
                 : "=r"(r[0]), "=r"(r[1]) : "r"(addr));
}
__device__ __forceinline__ void mma16816(float (&c)[4], const uint32_t (&a)[4],
                                         const uint32_t (&b)[2]) {
    asm volatile(
        "mma.sync.aligned.m16n8k16.row.col.f32.bf16.bf16.f32 "
        "{%0,%1,%2,%3}, {%4,%5,%6,%7}, {%8,%9}, {%0,%1,%2,%3};"
        : "+f"(c[0]), "+f"(c[1]), "+f"(c[2]), "+f"(c[3])
        : "r"(a[0]), "r"(a[1]), "r"(a[2]), "r"(a[3]), "r"(b[0]), "r"(b[1]));
}

// fp32 -> (bf16 hi, bf16 lo) split, two elements at a time
__device__ __forceinline__ void split2(float x0, float x1, uint32_t& hi2, uint32_t& lo2)
{
    asm("cvt.rn.bf16x2.f32 %0, %1, %2;" : "=r"(hi2) : "f"(x1), "f"(x0));
    float h0 = __uint_as_float(hi2 << 16);
    float h1 = __uint_as_float(hi2 & 0xffff0000u);
    asm("cvt.rn.bf16x2.f32 %0, %1, %2;" : "=r"(lo2) : "f"(x1 - h1), "f"(x0 - h0));
}
__device__ __forceinline__ uint32_t pack_bf2(float x0, float x1)
{
    uint32_t r;
    asm("cvt.rn.bf16x2.f32 %0, %1, %2;" : "=r"(r) : "f"(x1), "f"(x0));
    return r;
}

// ---------------------------------------------------------------------------
// fp32 -> bf16 hi/lo conversion (inputs & weights)
// ---------------------------------------------------------------------------
__global__ void convert_split(const float* __restrict__ src,
                              __nv_bfloat16* __restrict__ hi,
                              __nv_bfloat16* __restrict__ lo, int n4)
{
    int i = blockIdx.x * blockDim.x + threadIdx.x;
    if (i >= n4) return;
    float4 v = reinterpret_cast<const float4*>(src)[i];
    uint32_t h0, l0, h1, l1;
    split2(v.x, v.y, h0, l0);
    split2(v.z, v.w, h1, l1);
    reinterpret_cast<uint2*>(hi)[i] = make_uint2(h0, h1);
    reinterpret_cast<uint2*>(lo)[i] = make_uint2(l0, l1);
}

// ---------------------------------------------------------------------------
// Tensor-core bf16 multi-pass GEMM.
//   C[m,n] = alpha * sum_k A[m,k]*B[n,k]  (+ bias), fp32 accumulate.
//   TA=0: A gmem [m,k].  TA=1: A gmem [k,m].
//   TB=1: B gmem [n,k].  TB=0: B gmem [k,n].
//   OUT=0: fp32 C.  OUT=1: bf16 hi/lo pair C.  OUT=2: bf16 hi-only C.
//   AP: A is hi/lo pair.  BP: B is hi/lo pair.
//   Passes: ah*bh  (+ ah*bl if BP)  (+ al*bh if AP).
// ---------------------------------------------------------------------------
template <int TA, int TB, int BIAS, int BN, int OUT, int AP, int BP>
__global__ void __launch_bounds__(256, 2)
tgemm(const __nv_bfloat16* __restrict__ Ah_, const __nv_bfloat16* __restrict__ Al_,
      const __nv_bfloat16* __restrict__ Bh_, const __nv_bfloat16* __restrict__ Bl_,
      float* __restrict__ Cf,
      __nv_bfloat16* __restrict__ Ch, __nv_bfloat16* __restrict__ Cl,
      int lda, int ldb, int ldc,
      long long sAo, long long sAi, long long sBo, long long sBi,
      long long sCo, long long sCi, int zInner,
      const float* __restrict__ bias1, const float* __restrict__ bias2,
      long long sB2o, long long sB2i, float alpha, int K)
{
    extern __shared__ char smem[];
    constexpr int BM = 128, BK = 32;
    constexpr int A_SZ = (TA == 0) ? BM * 80 : BK * 272;
    constexpr int A_TOT = (AP ? 2 : 1) * A_SZ;
    constexpr int PB   = (TB == 1) ? 80 : (BN * 2 + 16);
    constexpr int B_SZ = (TB == 1) ? BN * 80 : BK * PB;
    constexpr int B_TOT = (BP ? 2 : 1) * B_SZ;
    constexpr int STAGE = A_TOT + B_TOT;
    constexpr int MI = (BN == 128) ? 4 : 2;
    constexpr int NI = 4;
    constexpr int WM = (BN == 128) ? 2 : 4;

    const int tid = threadIdx.x;
    const int lane = tid & 31, wid = tid >> 5;
    const int m_base = (wid % WM) * MI * 16;
    const int n_base = (wid / WM) * NI * 8;

    int z = blockIdx.z, zo = z / zInner, zi = z % zInner;
    Ah_ += zo * sAo + zi * sAi;
    if (AP) Al_ += zo * sAo + zi * sAi;
    Bh_ += zo * sBo + zi * sBi;
    if (BP) Bl_ += zo * sBo + zi * sBi;
    const long long coff = zo * sCo + zi * sCi;
    if (OUT == 0) Cf += coff; else { Ch += coff; if (OUT == 1) Cl += coff; }
    const float* b2 = (BIAS == 3) ? (bias2 + zo * sB2o + zi * sB2i) : nullptr;

    const int m0 = blockIdx.y * BM;
    const int n0 = blockIdx.x * BN;

    const uint32_t sb0 = smem_u32(smem);

    auto stage_in = [&](int c, uint32_t base) {
        const int k0 = c * BK;
        if (TA == 0) {
#pragma unroll
            for (int it = 0; it < (BM * 4) / 256; ++it) {
                int idx = tid + it * 256, r = idx >> 2, sg = idx & 3;
                uint32_t d = base + r * 80 + sg * 16;
                long long o = (long long)(m0 + r) * lda + k0 + sg * 8;
                CP16(d, Ah_ + o);
                if (AP) CP16(d + A_SZ, Al_ + o);
            }
        } else {
#pragma unroll
            for (int it = 0; it < (BK * 16) / 256; ++it) {
                int idx = tid + it * 256, kr = idx >> 4, sg = idx & 15;
                uint32_t d = base + kr * 272 + sg * 16;
                long long o = (long long)(k0 + kr) * lda + m0 + sg * 8;
                CP16(d, Ah_ + o);
                if (AP) CP16(d + A_SZ, Al_ + o);
            }
        }
        if (TB == 1) {
#pragma unroll
            for (int it = 0; it < (BN * 4) / 256; ++it) {
                int idx = tid + it * 256, r = idx >> 2, sg = idx & 3;
                uint32_t d = base + A_TOT + r * 80 + sg * 16;
                long long o = (long long)(n0 + r) * ldb + k0 + sg * 8;
                CP16(d, Bh_ + o);
                if (BP) CP16(d + B_SZ, Bl_ + o);
            }
        } else {
            constexpr int SEGS = BN / 8;
#pragma unroll
            for (int it = 0; it < (BK * SEGS) / 256; ++it) {
                int idx = tid + it * 256, kr = idx / SEGS, sg = idx % SEGS;
                uint32_t d = base + A_TOT + kr * PB + sg * 16;
                long long o = (long long)(k0 + kr) * ldb + n0 + sg * 8;
                CP16(d, Bh_ + o);
                if (BP) CP16(d + B_SZ, Bl_ + o);
            }
        }
    };

    float acc[MI][NI][4] = {};

    const int nch = K / BK;
    stage_in(0, sb0);
    CP_COMMIT();

    for (int c = 0; c < nch; ++c) {
        if (c + 1 < nch) stage_in(c + 1, sb0 + ((c + 1) & 1) * STAGE);
        CP_COMMIT();
        CP_WAIT1();
        __syncthreads();

        const uint32_t ab = sb0 + (c & 1) * STAGE;
        const uint32_t bb = ab + A_TOT;
#pragma unroll
        for (int ks = 0; ks < 2; ++ks) {
            const int kk = ks * 16;
            uint32_t bh[NI][2], bl[NI][2];
#pragma unroll
            for (int ni = 0; ni < NI; ++ni) {
                uint32_t addr;
                if (TB == 1) {
                    addr = bb + (n_base + ni * 8 + (lane & 7)) * 80 + (kk + ((lane >> 3) & 1) * 8) * 2;
                    ldsm_x2(bh[ni], addr);
                    if (BP) ldsm_x2(bl[ni], addr + B_SZ);
                } else {
                    addr = bb + (kk + (lane & 15)) * PB + (n_base + ni * 8) * 2;
                    ldsm_x2_t(bh[ni], addr);
                    if (BP) ldsm_x2_t(bl[ni], addr + B_SZ);
                }
            }
#pragma unroll
            for (int mi = 0; mi < MI; ++mi) {
                uint32_t ah[4], al[4], ad;
                if (TA == 0) {
                    ad = ab + (m_base + mi * 16 + (lane & 15)) * 80 + (kk + (lane >> 4) * 8) * 2;
                    ldsm_x4(ah, ad);
                    if (AP) ldsm_x4(al, ad + A_SZ);
                } else {
                    ad = ab + (kk + (lane & 7) + (lane >> 4) * 8) * 272
                            + (m_base + mi * 16 + ((lane >> 3) & 1) * 8) * 2;
                    ldsm_x4_t(ah, ad);
                    if (AP) ldsm_x4_t(al, ad + A_SZ);
                }
#pragma unroll
                for (int ni = 0; ni < NI; ++ni) {
                    mma16816(acc[mi][ni], ah, bh[ni]);
                    if (BP) mma16816(acc[mi][ni], ah, bl[ni]);
                    if (AP) mma16816(acc[mi][ni], al, bh[ni]);
                }
            }
        }
        __syncthreads();
    }

    // ---- epilogue ----
#pragma unroll
    for (int mi = 0; mi < MI; ++mi) {
#pragma unroll
        for (int ni = 0; ni < NI; ++ni) {
            int m = m0 + m_base + mi * 16 + (lane >> 2);
            int n = n0 + n_base + ni * 8 + 2 * (lane & 3);
            float v0 = acc[mi][ni][0] * alpha, v1 = acc[mi][ni][1] * alpha;
            float v2 = acc[mi][ni][2] * alpha, v3 = acc[mi][ni][3] * alpha;
            if (BIAS == 1) { float b = bias1[m], bb8 = bias1[m + 8]; v0 += b; v1 += b; v2 += bb8; v3 += bb8; }
            if (BIAS == 2) { float b = bias1[n], bb1 = bias1[n + 1]; v0 += b; v1 += bb1; v2 += b; v3 += bb1; }
            if (BIAS == 3) {
                float c0 = b2[n], c1 = b2[n + 1];
                float bm = bias1[m], bm8 = bias1[m + 8];
                v0 += bm * c0; v1 += bm * c1; v2 += bm8 * c0; v3 += bm8 * c1;
            }
            if (OUT == 0) {
                *reinterpret_cast<float2*>(&Cf[(long long)m * ldc + n]) = make_float2(v0, v1);
                *reinterpret_cast<float2*>(&Cf[(long long)(m + 8) * ldc + n]) = make_float2(v2, v3);
            } else if (OUT == 1) {
                uint32_t h, l;
                split2(v0, v1, h, l);
                *reinterpret_cast<uint32_t*>(&Ch[(long long)m * ldc + n]) = h;
                *reinterpret_cast<uint32_t*>(&Cl[(long long)m * ldc + n]) = l;
                split2(v2, v3, h, l);
                *reinterpret_cast<uint32_t*>(&Ch[(long long)(m + 8) * ldc + n]) = h;
                *reinterpret_cast<uint32_t*>(&Cl[(long long)(m + 8) * ldc + n]) = l;
            } else {
                *reinterpret_cast<uint32_t*>(&Ch[(long long)m * ldc + n]) = pack_bf2(v0, v1);
                *reinterpret_cast<uint32_t*>(&Ch[(long long)(m + 8) * ldc + n]) = pack_bf2(v2, v3);
            }
        }
    }
}

// ---------------------------------------------------------------------------
// Fast exp via FMA polynomial
// ---------------------------------------------------------------------------
__device__ __forceinline__ float fexp(float x)
{
    float t = x * 1.4426950408889634f;
    float k = rintf(t);
    float f = (t - k) * 0.6931471805599453f;
    float p = 1.0f + f * (1.0f + f * (0.5f + f * (0.166666667f +
                     f * (0.0416666668f + f * 0.00833333340f))));
    return __int_as_float(((int)k + 127) << 23) * p;
}

// Row softmax: bf16 scores in, bf16 probs out (hi only). One block per row.
__global__ void softmax_rows(const __nv_bfloat16* __restrict__ a,
                             __nv_bfloat16* __restrict__ ph)
{
    const uint32_t* p32 = reinterpret_cast<const uint32_t*>(a) + (long long)blockIdx.x * (SEQ / 2);
    int t = threadIdx.x;
    int w = t >> 5, lane = t & 31;

    float2 v[4];
    float m = -1e30f;
#pragma unroll
    for (int i = 0; i < 4; i++) {
        uint32_t u = p32[t + i * 256];
        v[i] = __bfloat1622float2(*reinterpret_cast<__nv_bfloat162*>(&u));
        m = fmaxf(m, fmaxf(v[i].x, v[i].y));
    }
#pragma unroll
    for (int o = 16; o; o >>= 1) m = fmaxf(m, __shfl_xor_sync(0xffffffffu, m, o));

    __shared__ float red[8];
    if (lane == 0) red[w] = m;
    __syncthreads();
    float bm = red[0];
#pragma unroll
    for (int i = 1; i < 8; i++) bm = fmaxf(bm, red[i]);
    __syncthreads();

    float s = 0.f;
#pragma unroll
    for (int i = 0; i < 4; i++) {
        v[i].x = fexp(v[i].x - bm);
        v[i].y = fexp(v[i].y - bm);
        s += v[i].x + v[i].y;
    }
#pragma unroll
    for (int o = 16; o; o >>= 1) s += __shfl_xor_sync(0xffffffffu, s, o);
    if (lane == 0) red[w] = s;
    __syncthreads();
    float bs = red[0];
#pragma unroll
    for (int i = 1; i < 8; i++) bs += red[i];

    float inv = 1.0f / bs;
    uint32_t* hp = reinterpret_cast<uint32_t*>(ph) + (long long)blockIdx.x * (SEQ / 2);
#pragma unroll
    for (int i = 0; i < 4; i++)
        hp[t + i * 256] = pack_bf2(v[i].x * inv, v[i].y * inv);
}

// S[b*CDIM + c] = sum_t v[b, t, c]
__global__ void colsum_v(const __nv_bfloat16* __restrict__ vh,
                         const __nv_bfloat16* __restrict__ vl,
                         float* __restrict__ s)
{
    int idx = blockIdx.x * blockDim.x + threadIdx.x;
    if (idx >= NB_ * CDIM) return;
    int b = idx >> 10, c = idx & (CDIM - 1);
    long long base = (long long)b * SEQ * CDIM + c;
    float acc = 0.f;
#pragma unroll 8
    for (int t = 0; t < SEQ; t++) {
        long long o = base + (long long)t * CDIM;
        acc += __bfloat162float(vh[o]) + __bfloat162float(vl[o]);
    }
    s[idx] = acc;
}

// ---------------------------------------------------------------------------
// Launch
// ---------------------------------------------------------------------------
extern "C" void kernel_launch(void* const* d_in, const int* in_sizes, int n_in,
                              void* d_out, int out_size)
{
    const float* x      = (const float*)d_in[0];
    const float* w_hseq = (const float*)d_in[1];
    const float* b_hseq = (const float*)d_in[2];
    const float* wq     = (const float*)d_in[3];
    const float* bq     = (const float*)d_in[4];
    const float* wk     = (const float*)d_in[5];
    const float* bk     = (const float*)d_in[6];
    const float* wv     = (const float*)d_in[7];
    const float* bv     = (const float*)d_in[8];
    const float* w_oseq = (const float*)d_in[9];
    const float* b_oseq = (const float*)d_in[10];
    float* out = (float*)d_out;

    __nv_bfloat16 *xbh, *xbl, *whh, *whl, *wqh, *wql, *wkh, *wkl, *wvh, *wvl, *woh, *wol;
    __nv_bfloat16 *xhh, *xhl, *qh, *ql, *kh, *kl, *vh, *vl, *pph, *zh, *zl, *attn;
    float *sv;
    cudaGetSymbolAddress((void**)&xbh, g_xb_h);  cudaGetSymbolAddress((void**)&xbl, g_xb_l);
    cudaGetSymbolAddress((void**)&whh, g_whs_h); cudaGetSymbolAddress((void**)&whl, g_whs_l);
    cudaGetSymbolAddress((void**)&wqh, g_wq_h);  cudaGetSymbolAddress((void**)&wql, g_wq_l);
    cudaGetSymbolAddress((void**)&wkh, g_wk_h);  cudaGetSymbolAddress((void**)&wkl, g_wk_l);
    cudaGetSymbolAddress((void**)&wvh, g_wv_h);  cudaGetSymbolAddress((void**)&wvl, g_wv_l);
    cudaGetSymbolAddress((void**)&woh, g_wo_h);  cudaGetSymbolAddress((void**)&wol, g_wo_l);
    cudaGetSymbolAddress((void**)&xhh, g_xh_h);  cudaGetSymbolAddress((void**)&xhl, g_xh_l);
    cudaGetSymbolAddress((void**)&qh,  g_q_h);   cudaGetSymbolAddress((void**)&ql,  g_q_l);
    cudaGetSymbolAddress((void**)&kh,  g_k_h);   cudaGetSymbolAddress((void**)&kl,  g_k_l);
    cudaGetSymbolAddress((void**)&vh,  g_v_h);   cudaGetSymbolAddress((void**)&vl,  g_v_l);
    cudaGetSymbolAddress((void**)&pph, g_p_h);
    cudaGetSymbolAddress((void**)&zh,  g_z_h);   cudaGetSymbolAddress((void**)&zl,  g_z_l);
    cudaGetSymbolAddress((void**)&attn, g_attn);
    cudaGetSymbolAddress((void**)&sv,   g_s);

    const long long sBT = (long long)SEQ * CDIM;
    const long long sAh_ = (long long)SEQ * SEQ;
    const long long sAb = (long long)NH * SEQ * SEQ;
    const long long sZh_ = (long long)SEQ * HD;
    const long long sZb = (long long)NH * SEQ * HD;

    convert_split<<<(int)(E_X / 4 / 256), 256>>>(x, xbh, xbl, (int)(E_X / 4));
    convert_split<<<(int)(E_WS / 4 / 256), 256>>>(w_hseq, whh, whl, (int)(E_WS / 4));
    convert_split<<<(int)(E_W / 4 / 256), 256>>>(wq, wqh, wql, (int)(E_W / 4));
    convert_split<<<(int)(E_W / 4 / 256), 256>>>(wk, wkh, wkl, (int)(E_W / 4));
    convert_split<<<(int)(E_W / 4 / 256), 256>>>(wv, wvh, wvl, (int)(E_W / 4));
    convert_split<<<(int)(E_WS / 4 / 256), 256>>>(w_oseq, woh, wol, (int)(E_WS / 4));

    // smem: 2 stages of (A_TOT + B_TOT)
    const int SM_A = 2 * (2 * 10240 + 2 * 8704);   // 75776  <0,0,1,128,1,1,1>
    const int SM_B = 2 * (2 * 10240 + 2 * 10240);  // 81920  <0,1,2,128,1,1,1>
    const int SM_C = 2 * (10240 + 10240);          // 40960  <0,1,0,128,2,0,0>
    const int SM_E = 2 * (8704 + 2 * 4608);        // 35840  <1,0,0,64,1,0,1>
    const int SM_F = 2 * (2 * 10240 + 2 * 4608);   // 59392  <0,0,3,64,0,1,1>

    cudaFuncSetAttribute(tgemm<0, 0, 1, 128, 1, 1, 1>, cudaFuncAttributeMaxDynamicSharedMemorySize, SM_A);
    cudaFuncSetAttribute(tgemm<0, 1, 2, 128, 1, 1, 1>, cudaFuncAttributeMaxDynamicSharedMemorySize, SM_B);
    cudaFuncSetAttribute(tgemm<0, 1, 0, 128, 2, 0, 0>, cudaFuncAttributeMaxDynamicSharedMemorySize, SM_C);
    cudaFuncSetAttribute(tgemm<1, 0, 0, 64, 1, 0, 1>,  cudaFuncAttributeMaxDynamicSharedMemorySize, SM_E);
    cudaFuncSetAttribute(tgemm<0, 0, 3, 64, 0, 1, 1>,  cudaFuncAttributeMaxDynamicSharedMemorySize, SM_F);

    // Stage A: xh[b,t,c] = sum_s w_hseq[t,s]*x[b,s,c] + b_hseq[t]  -> bf16 pair
    tgemm<0, 0, 1, 128, 1, 1, 1><<<dim3(CDIM / 128, SEQ / 128, NB_), 256, SM_A>>>(
        whh, whl, xbh, xbl, nullptr, xhh, xhl,
        SEQ, CDIM, CDIM, 0, 0, sBT, 0, sBT, 0, 1,
        b_hseq, nullptr, 0, 0, 1.0f, SEQ);

    // Stage B: q/k/v[b,t,o] = xh @ W^T + bias  -> bf16 pairs
    tgemm<0, 1, 2, 128, 1, 1, 1><<<dim3(CDIM / 128, (NB_ * SEQ) / 128, 1), 256, SM_B>>>(
        xhh, xhl, wqh, wql, nullptr, qh, ql,
        CDIM, CDIM, CDIM, 0, 0, 0, 0, 0, 0, 1,
        bq, nullptr, 0, 0, 1.0f, CDIM);
    tgemm<0, 1, 2, 128, 1, 1, 1><<<dim3(CDIM / 128, (NB_ * SEQ) / 128, 1), 256, SM_B>>>(
        xhh, xhl, wkh, wkl, nullptr, kh, kl,
        CDIM, CDIM, CDIM, 0, 0, 0, 0, 0, 0, 1,
        bk, nullptr, 0, 0, 1.0f, CDIM);
    tgemm<0, 1, 2, 128, 1, 1, 1><<<dim3(CDIM / 128, (NB_ * SEQ) / 128, 1), 256, SM_B>>>(
        xhh, xhl, wvh, wvl, nullptr, vh, vl,
        CDIM, CDIM, CDIM, 0, 0, 0, 0, 0, 0, 1,
        bv, nullptr, 0, 0, 1.0f, CDIM);

    // Stage C: scores = (1/8) q.k  -> bf16 (single-pass: q_h x k_h only)
    tgemm<0, 1, 0, 128, 2, 0, 0><<<dim3(SEQ / 128, SEQ / 128, NB_ * NH), 256, SM_C>>>(
        qh, nullptr, kh, nullptr, nullptr, attn, nullptr,
        CDIM, CDIM, SEQ, sBT, HD, sBT, HD, sAb, sAh_, NH,
        nullptr, nullptr, 0, 0, 0.125f, HD);

    // Stage D: softmax -> bf16 probs (hi only)
    softmax_rows<<<NB_ * NH * SEQ, 256>>>(attn, pph);

    // Column sums of v (rank-1 bias term)
    colsum_v<<<(NB_ * CDIM + 255) / 256, 256>>>(vh, vl, sv);

    // Stage E: Z[b,h,kj,d] = sum_q p[q,kj]*v[q,h*64+d]  -> bf16 pair (p single, v pair)
    tgemm<1, 0, 0, 64, 1, 0, 1><<<dim3(1, SEQ / 128, NB_ * NH), 256, SM_E>>>(
        pph, nullptr, vh, vl, nullptr, zh, zl,
        SEQ, CDIM, HD, sAb, sAh_, sBT, HD, sZb, sZh_, NH,
        nullptr, nullptr, 0, 0, 1.0f, SEQ);

    // Stage F: out = w_oseq @ Z + b_oseq*S
    tgemm<0, 0, 3, 64, 0, 1, 1><<<dim3(1, SEQ / 128, NB_ * NH), 256, SM_F>>>(
        woh, wol, zh, zl, out, nullptr, nullptr,
        SEQ, HD, CDIM, 0, 0, sZb, sZh_, sBT, HD, NH,
        b_oseq, sv, CDIM, HD, 1.0f, SEQ);
}

// round 8
// speedup vs baseline: 3.8922x; 1.4360x over previous
#include <cuda_runtime.h>
#include <cuda_bf16.h>
#include <cstdint>

// Problem constants
#define NB_   2
#define SEQ  2048
#define CDIM 1024
#define NH   16
#define HD   64

// ---------------------------------------------------------------------------
// Static device scratch
// ---------------------------------------------------------------------------
#define E_X   ((size_t)NB_ * SEQ * CDIM)      // 4M elems
#define E_WS  ((size_t)SEQ * SEQ)             // 4M
#define E_W   ((size_t)CDIM * CDIM)           // 1M
#define E_P   ((size_t)NB_ * NH * SEQ * SEQ)  // 134M
#define E_Z   ((size_t)NB_ * NH * SEQ * HD)   // 4M

__device__ __nv_bfloat16 g_xb_h[E_X],  g_xb_l[E_X];
__device__ __nv_bfloat16 g_whs_h[E_WS], g_whs_l[E_WS];
__device__ __nv_bfloat16 g_wq_h[E_W];
__device__ __nv_bfloat16 g_wk_h[E_W];
__device__ __nv_bfloat16 g_wv_h[E_W];
__device__ __nv_bfloat16 g_wo_h[E_WS];
__device__ __nv_bfloat16 g_xh_h[E_X],  g_xh_l[E_X];
__device__ __nv_bfloat16 g_q_h[E_X];
__device__ __nv_bfloat16 g_k_h[E_X];
__device__ __nv_bfloat16 g_v_h[E_X];
__device__ __nv_bfloat16 g_attn[E_P];               // bf16 scores (256 MB)
__device__ __nv_bfloat16 g_p_h[E_P];                // bf16 probs (256 MB)
__device__ __nv_bfloat16 g_z_h[E_Z];
__device__ float         g_sxh[(size_t)NB_ * CDIM]; // colsum of xh (precise)
__device__ float         g_s[(size_t)NB_ * CDIM];   // colsum of v (analytic)

// ---------------------------------------------------------------------------
// Primitives
// ---------------------------------------------------------------------------
__device__ __forceinline__ uint32_t smem_u32(const void* p) {
    uint32_t a;
    asm("{ .reg .u64 t; cvta.to.shared.u64 t, %1; cvt.u32.u64 %0, t; }" : "=r"(a) : "l"(p));
    return a;
}
#define CP16(d, s) asm volatile("cp.async.cg.shared.global [%0], [%1], 16;" :: "r"(d), "l"(s))
#define CP_COMMIT() asm volatile("cp.async.commit_group;" ::: "memory")
#define CP_WAIT1()  asm volatile("cp.async.wait_group 1;" ::: "memory")

__device__ __forceinline__ void ldsm_x4(uint32_t (&r)[4], uint32_t addr) {
    asm volatile("ldmatrix.sync.aligned.m8n8.x4.shared.b16 {%0,%1,%2,%3}, [%4];"
                 : "=r"(r[0]), "=r"(r[1]), "=r"(r[2]), "=r"(r[3]) : "r"(addr));
}
__device__ __forceinline__ void ldsm_x4_t(uint32_t (&r)[4], uint32_t addr) {
    asm volatile("ldmatrix.sync.aligned.m8n8.x4.trans.shared.b16 {%0,%1,%2,%3}, [%4];"
                 : "=r"(r[0]), "=r"(r[1]), "=r"(r[2]), "=r"(r[3]) : "r"(addr));
}
__device__ __forceinline__ void ldsm_x2(uint32_t (&r)[2], uint32_t addr) {
    asm volatile("ldmatrix.sync.aligned.m8n8.x2.shared.b16 {%0,%1}, [%2];"
                 : "=r"(r[0]), "=r"(r[1]) : "r"(addr));
}
__device__ __forceinline__ void ldsm_x2_t(uint32_t (&r)[2], uint32_t addr) {
    asm volatile("ldmatrix.sync.aligned.m8n8.x2.trans.shared.b16 {%0,%1}, [%2];"
                 : "=r"(r[0]), "=r"(r[1]) : "r"(addr));
}
__device__ __forceinline__ void mma16816(float (&c)[4], const uint32_t (&a)[4],
                                         const uint32_t (&b)[2]) {
    asm volatile(
        "mma.sync.aligned.m16n8k16.row.col.f32.bf16.bf16.f32 "
        "{%0,%1,%2,%3}, {%4,%5,%6,%7}, {%8,%9}, {%0,%1,%2,%3};"
        : "+f"(c[0]), "+f"(c[1]), "+f"(c[2]), "+f"(c[3])
        : "r"(a[0]), "r"(a[1]), "r"(a[2]), "r"(a[3]), "r"(b[0]), "r"(b[1]));
}

// fp32 -> (bf16 hi, bf16 lo) split, two elements at a time
__device__ __forceinline__ void split2(float x0, float x1, uint32_t& hi2, uint32_t& lo2)
{
    asm("cvt.rn.bf16x2.f32 %0, %1, %2;" : "=r"(hi2) : "f"(x1), "f"(x0));
    float h0 = __uint_as_float(hi2 << 16);
    float h1 = __uint_as_float(hi2 & 0xffff0000u);
    asm("cvt.rn.bf16x2.f32 %0, %1, %2;" : "=r"(lo2) : "f"(x1 - h1), "f"(x0 - h0));
}
__device__ __forceinline__ uint32_t pack_bf2(float x0, float x1)
{
    uint32_t r;
    asm("cvt.rn.bf16x2.f32 %0, %1, %2;" : "=r"(r) : "f"(x1), "f"(x0));
    return r;
}

// ---------------------------------------------------------------------------
// Conversions
// ---------------------------------------------------------------------------
__global__ void convert_split(const float* __restrict__ src,
                              __nv_bfloat16* __restrict__ hi,
                              __nv_bfloat16* __restrict__ lo, int n4)
{
    int i = blockIdx.x * blockDim.x + threadIdx.x;
    if (i >= n4) return;
    float4 v = reinterpret_cast<const float4*>(src)[i];
    uint32_t h0, l0, h1, l1;
    split2(v.x, v.y, h0, l0);
    split2(v.z, v.w, h1, l1);
    reinterpret_cast<uint2*>(hi)[i] = make_uint2(h0, h1);
    reinterpret_cast<uint2*>(lo)[i] = make_uint2(l0, l1);
}

__global__ void convert_hi(const float* __restrict__ src,
                           __nv_bfloat16* __restrict__ hi, int n4)
{
    int i = blockIdx.x * blockDim.x + threadIdx.x;
    if (i >= n4) return;
    float4 v = reinterpret_cast<const float4*>(src)[i];
    reinterpret_cast<uint2*>(hi)[i] =
        make_uint2(pack_bf2(v.x, v.y), pack_bf2(v.z, v.w));
}

// ---------------------------------------------------------------------------
// Tensor-core bf16 multi-pass GEMM.
//   C[m,n] = alpha * sum_k A[m,k]*B[n,k]  (+ bias), fp32 accumulate.
//   TA=0: A gmem [m,k].  TA=1: A gmem [k,m].
//   TB=1: B gmem [n,k].  TB=0: B gmem [k,n].
//   OUT=0: fp32 C.  OUT=1: bf16 hi/lo pair C.  OUT=2: bf16 hi-only C.
//   AP: A is hi/lo pair.  BP: B is hi/lo pair.
//   Passes: ah*bh  (+ ah*bl if BP)  (+ al*bh if AP).
// ---------------------------------------------------------------------------
template <int TA, int TB, int BIAS, int BN, int OUT, int AP, int BP>
__global__ void __launch_bounds__(256, 2)
tgemm(const __nv_bfloat16* __restrict__ Ah_, const __nv_bfloat16* __restrict__ Al_,
      const __nv_bfloat16* __restrict__ Bh_, const __nv_bfloat16* __restrict__ Bl_,
      float* __restrict__ Cf,
      __nv_bfloat16* __restrict__ Ch, __nv_bfloat16* __restrict__ Cl,
      int lda, int ldb, int ldc,
      long long sAo, long long sAi, long long sBo, long long sBi,
      long long sCo, long long sCi, int zInner,
      const float* __restrict__ bias1, const float* __restrict__ bias2,
      long long sB2o, long long sB2i, float alpha, int K)
{
    extern __shared__ char smem[];
    constexpr int BM = 128, BK = 32;
    constexpr int A_SZ = (TA == 0) ? BM * 80 : BK * 272;
    constexpr int A_TOT = (AP ? 2 : 1) * A_SZ;
    constexpr int PB   = (TB == 1) ? 80 : (BN * 2 + 16);
    constexpr int B_SZ = (TB == 1) ? BN * 80 : BK * PB;
    constexpr int B_TOT = (BP ? 2 : 1) * B_SZ;
    constexpr int STAGE = A_TOT + B_TOT;
    constexpr int MI = (BN == 128) ? 4 : 2;
    constexpr int NI = 4;
    constexpr int WM = (BN == 128) ? 2 : 4;

    const int tid = threadIdx.x;
    const int lane = tid & 31, wid = tid >> 5;
    const int m_base = (wid % WM) * MI * 16;
    const int n_base = (wid / WM) * NI * 8;

    int z = blockIdx.z, zo = z / zInner, zi = z % zInner;
    Ah_ += zo * sAo + zi * sAi;
    if (AP) Al_ += zo * sAo + zi * sAi;
    Bh_ += zo * sBo + zi * sBi;
    if (BP) Bl_ += zo * sBo + zi * sBi;
    const long long coff = zo * sCo + zi * sCi;
    if (OUT == 0) Cf += coff; else { Ch += coff; if (OUT == 1) Cl += coff; }
    const float* b2 = (BIAS == 3) ? (bias2 + zo * sB2o + zi * sB2i) : nullptr;

    const int m0 = blockIdx.y * BM;
    const int n0 = blockIdx.x * BN;

    const uint32_t sb0 = smem_u32(smem);

    auto stage_in = [&](int c, uint32_t base) {
        const int k0 = c * BK;
        if (TA == 0) {
#pragma unroll
            for (int it = 0; it < (BM * 4) / 256; ++it) {
                int idx = tid + it * 256, r = idx >> 2, sg = idx & 3;
                uint32_t d = base + r * 80 + sg * 16;
                long long o = (long long)(m0 + r) * lda + k0 + sg * 8;
                CP16(d, Ah_ + o);
                if (AP) CP16(d + A_SZ, Al_ + o);
            }
        } else {
#pragma unroll
            for (int it = 0; it < (BK * 16) / 256; ++it) {
                int idx = tid + it * 256, kr = idx >> 4, sg = idx & 15;
                uint32_t d = base + kr * 272 + sg * 16;
                long long o = (long long)(k0 + kr) * lda + m0 + sg * 8;
                CP16(d, Ah_ + o);
                if (AP) CP16(d + A_SZ, Al_ + o);
            }
        }
        if (TB == 1) {
#pragma unroll
            for (int it = 0; it < (BN * 4) / 256; ++it) {
                int idx = tid + it * 256, r = idx >> 2, sg = idx & 3;
                uint32_t d = base + A_TOT + r * 80 + sg * 16;
                long long o = (long long)(n0 + r) * ldb + k0 + sg * 8;
                CP16(d, Bh_ + o);
                if (BP) CP16(d + B_SZ, Bl_ + o);
            }
        } else {
            constexpr int SEGS = BN / 8;
#pragma unroll
            for (int it = 0; it < (BK * SEGS) / 256; ++it) {
                int idx = tid + it * 256, kr = idx / SEGS, sg = idx % SEGS;
                uint32_t d = base + A_TOT + kr * PB + sg * 16;
                long long o = (long long)(k0 + kr) * ldb + n0 + sg * 8;
                CP16(d, Bh_ + o);
                if (BP) CP16(d + B_SZ, Bl_ + o);
            }
        }
    };

    float acc[MI][NI][4] = {};

    const int nch = K / BK;
    stage_in(0, sb0);
    CP_COMMIT();

    for (int c = 0; c < nch; ++c) {
        if (c + 1 < nch) stage_in(c + 1, sb0 + ((c + 1) & 1) * STAGE);
        CP_COMMIT();
        CP_WAIT1();
        __syncthreads();

        const uint32_t ab = sb0 + (c & 1) * STAGE;
        const uint32_t bb = ab + A_TOT;
#pragma unroll
        for (int ks = 0; ks < 2; ++ks) {
            const int kk = ks * 16;
            uint32_t bh[NI][2], bl[NI][2];
#pragma unroll
            for (int ni = 0; ni < NI; ++ni) {
                uint32_t addr;
                if (TB == 1) {
                    addr = bb + (n_base + ni * 8 + (lane & 7)) * 80 + (kk + ((lane >> 3) & 1) * 8) * 2;
                    ldsm_x2(bh[ni], addr);
                    if (BP) ldsm_x2(bl[ni], addr + B_SZ);
                } else {
                    addr = bb + (kk + (lane & 15)) * PB + (n_base + ni * 8) * 2;
                    ldsm_x2_t(bh[ni], addr);
                    if (BP) ldsm_x2_t(bl[ni], addr + B_SZ);
                }
            }
#pragma unroll
            for (int mi = 0; mi < MI; ++mi) {
                uint32_t ah[4], al[4], ad;
                if (TA == 0) {
                    ad = ab + (m_base + mi * 16 + (lane & 15)) * 80 + (kk + (lane >> 4) * 8) * 2;
                    ldsm_x4(ah, ad);
                    if (AP) ldsm_x4(al, ad + A_SZ);
                } else {
                    ad = ab + (kk + (lane & 7) + (lane >> 4) * 8) * 272
                            + (m_base + mi * 16 + ((lane >> 3) & 1) * 8) * 2;
                    ldsm_x4_t(ah, ad);
                    if (AP) ldsm_x4_t(al, ad + A_SZ);
                }
#pragma unroll
                for (int ni = 0; ni < NI; ++ni) {
                    mma16816(acc[mi][ni], ah, bh[ni]);
                    if (BP) mma16816(acc[mi][ni], ah, bl[ni]);
                    if (AP) mma16816(acc[mi][ni], al, bh[ni]);
                }
            }
        }
        __syncthreads();
    }

    // ---- epilogue ----
#pragma unroll
    for (int mi = 0; mi < MI; ++mi) {
#pragma unroll
        for (int ni = 0; ni < NI; ++ni) {
            int m = m0 + m_base + mi * 16 + (lane >> 2);
            int n = n0 + n_base + ni * 8 + 2 * (lane & 3);
            float v0 = acc[mi][ni][0] * alpha, v1 = acc[mi][ni][1] * alpha;
            float v2 = acc[mi][ni][2] * alpha, v3 = acc[mi][ni][3] * alpha;
            if (BIAS == 1) { float b = bias1[m], bb8 = bias1[m + 8]; v0 += b; v1 += b; v2 += bb8; v3 += bb8; }
            if (BIAS == 2) { float b = bias1[n], bb1 = bias1[n + 1]; v0 += b; v1 += bb1; v2 += b; v3 += bb1; }
            if (BIAS == 3) {
                float c0 = b2[n], c1 = b2[n + 1];
                float bm = bias1[m], bm8 = bias1[m + 8];
                v0 += bm * c0; v1 += bm * c1; v2 += bm8 * c0; v3 += bm8 * c1;
            }
            if (OUT == 0) {
                *reinterpret_cast<float2*>(&Cf[(long long)m * ldc + n]) = make_float2(v0, v1);
                *reinterpret_cast<float2*>(&Cf[(long long)(m + 8) * ldc + n]) = make_float2(v2, v3);
            } else if (OUT == 1) {
                uint32_t h, l;
                split2(v0, v1, h, l);
                *reinterpret_cast<uint32_t*>(&Ch[(long long)m * ldc + n]) = h;
                *reinterpret_cast<uint32_t*>(&Cl[(long long)m * ldc + n]) = l;
                split2(v2, v3, h, l);
                *reinterpret_cast<uint32_t*>(&Ch[(long long)(m + 8) * ldc + n]) = h;
                *reinterpret_cast<uint32_t*>(&Cl[(long long)(m + 8) * ldc + n]) = l;
            } else {
                *reinterpret_cast<uint32_t*>(&Ch[(long long)m * ldc + n]) = pack_bf2(v0, v1);
                *reinterpret_cast<uint32_t*>(&Ch[(long long)(m + 8) * ldc + n]) = pack_bf2(v2, v3);
            }
        }
    }
}

// ---------------------------------------------------------------------------
// Fast exp via FMA polynomial
// ---------------------------------------------------------------------------
__device__ __forceinline__ float fexp(float x)
{
    float t = x * 1.4426950408889634f;
    float k = rintf(t);
    float f = (t - k) * 0.6931471805599453f;
    float p = 1.0f + f * (1.0f + f * (0.5f + f * (0.166666667f +
                     f * (0.0416666668f + f * 0.00833333340f))));
    return __int_as_float(((int)k + 127) << 23) * p;
}

// Row softmax: bf16 scores in, bf16 probs out (hi only). One block per row.
__global__ void softmax_rows(const __nv_bfloat16* __restrict__ a,
                             __nv_bfloat16* __restrict__ ph)
{
    const uint32_t* p32 = reinterpret_cast<const uint32_t*>(a) + (long long)blockIdx.x * (SEQ / 2);
    int t = threadIdx.x;
    int w = t >> 5, lane = t & 31;

    float2 v[4];
    float m = -1e30f;
#pragma unroll
    for (int i = 0; i < 4; i++) {
        uint32_t u = p32[t + i * 256];
        v[i] = __bfloat1622float2(*reinterpret_cast<__nv_bfloat162*>(&u));
        m = fmaxf(m, fmaxf(v[i].x, v[i].y));
    }
#pragma unroll
    for (int o = 16; o; o >>= 1) m = fmaxf(m, __shfl_xor_sync(0xffffffffu, m, o));

    __shared__ float red[8];
    if (lane == 0) red[w] = m;
    __syncthreads();
    float bm = red[0];
#pragma unroll
    for (int i = 1; i < 8; i++) bm = fmaxf(bm, red[i]);
    __syncthreads();

    float s = 0.f;
#pragma unroll
    for (int i = 0; i < 4; i++) {
        v[i].x = fexp(v[i].x - bm);
        v[i].y = fexp(v[i].y - bm);
        s += v[i].x + v[i].y;
    }
#pragma unroll
    for (int o = 16; o; o >>= 1) s += __shfl_xor_sync(0xffffffffu, s, o);
    if (lane == 0) red[w] = s;
    __syncthreads();
    float bs = red[0];
#pragma unroll
    for (int i = 1; i < 8; i++) bs += red[i];

    float inv = 1.0f / bs;
    uint32_t* hp = reinterpret_cast<uint32_t*>(ph) + (long long)blockIdx.x * (SEQ / 2);
#pragma unroll
    for (int i = 0; i < 4; i++)
        hp[t + i * 256] = pack_bf2(v[i].x * inv, v[i].y * inv);
}

// sxh[b*CDIM + c] = sum_t (xh_h + xh_l)[b, t, c]   (precise colsum of xh)
__global__ void colsum_xh(const __nv_bfloat16* __restrict__ xhh,
                          const __nv_bfloat16* __restrict__ xhl,
                          float* __restrict__ s)
{
    int idx = blockIdx.x * blockDim.x + threadIdx.x;
    if (idx >= NB_ * CDIM) return;
    int b = idx >> 10, c = idx & (CDIM - 1);
    long long base = (long long)b * SEQ * CDIM + c;
    float acc = 0.f;
#pragma unroll 8
    for (int t = 0; t < SEQ; t++) {
        long long o = base + (long long)t * CDIM;
        acc += __bfloat162float(xhh[o]) + __bfloat162float(xhl[o]);
    }
    s[idx] = acc;
}

// S[b, c'] = sum_c sxh[b,c] * wv[c',c] + SEQ * bv[c']   (fp32, warp per output)
__global__ void s_from_xh(const float* __restrict__ sxh,
                          const float* __restrict__ wv,
                          const float* __restrict__ bv,
                          float* __restrict__ s)
{
    int o = blockIdx.x * 8 + (threadIdx.x >> 5);   // 0 .. NB_*CDIM-1
    int lane = threadIdx.x & 31;
    int b = o >> 10, cp = o & (CDIM - 1);
    const float* xr = sxh + (long long)b * CDIM;
    const float* wr = wv + (long long)cp * CDIM;
    float acc = 0.f;
#pragma unroll 8
    for (int c = lane; c < CDIM; c += 32) acc += xr[c] * wr[c];
#pragma unroll
    for (int off = 16; off; off >>= 1) acc += __shfl_xor_sync(0xffffffffu, acc, off);
    if (lane == 0) s[o] = acc + (float)SEQ * bv[cp];
}

// ---------------------------------------------------------------------------
// Launch
// ---------------------------------------------------------------------------
extern "C" void kernel_launch(void* const* d_in, const int* in_sizes, int n_in,
                              void* d_out, int out_size)
{
    const float* x      = (const float*)d_in[0];
    const float* w_hseq = (const float*)d_in[1];
    const float* b_hseq = (const float*)d_in[2];
    const float* wq     = (const float*)d_in[3];
    const float* bq     = (const float*)d_in[4];
    const float* wk     = (const float*)d_in[5];
    const float* bk     = (const float*)d_in[6];
    const float* wv     = (const float*)d_in[7];
    const float* bv     = (const float*)d_in[8];
    const float* w_oseq = (const float*)d_in[9];
    const float* b_oseq = (const float*)d_in[10];
    float* out = (float*)d_out;

    __nv_bfloat16 *xbh, *xbl, *whh, *whl, *wqh, *wkh, *wvh, *woh;
    __nv_bfloat16 *xhh, *xhl, *qh, *kh, *vh, *pph, *zh, *attn;
    float *sv, *sxh;
    cudaGetSymbolAddress((void**)&xbh, g_xb_h);  cudaGetSymbolAddress((void**)&xbl, g_xb_l);
    cudaGetSymbolAddress((void**)&whh, g_whs_h); cudaGetSymbolAddress((void**)&whl, g_whs_l);
    cudaGetSymbolAddress((void**)&wqh, g_wq_h);
    cudaGetSymbolAddress((void**)&wkh, g_wk_h);
    cudaGetSymbolAddress((void**)&wvh, g_wv_h);
    cudaGetSymbolAddress((void**)&woh, g_wo_h);
    cudaGetSymbolAddress((void**)&xhh, g_xh_h);  cudaGetSymbolAddress((void**)&xhl, g_xh_l);
    cudaGetSymbolAddress((void**)&qh,  g_q_h);
    cudaGetSymbolAddress((void**)&kh,  g_k_h);
    cudaGetSymbolAddress((void**)&vh,  g_v_h);
    cudaGetSymbolAddress((void**)&pph, g_p_h);
    cudaGetSymbolAddress((void**)&zh,  g_z_h);
    cudaGetSymbolAddress((void**)&attn, g_attn);
    cudaGetSymbolAddress((void**)&sxh,  g_sxh);
    cudaGetSymbolAddress((void**)&sv,   g_s);

    const long long sBT = (long long)SEQ * CDIM;
    const long long sAh_ = (long long)SEQ * SEQ;
    const long long sAb = (long long)NH * SEQ * SEQ;
    const long long sZh_ = (long long)SEQ * HD;
    const long long sZb = (long long)NH * SEQ * HD;

    // converts: x and w_hseq need pairs (stage A 3-pass); others hi-only
    convert_split<<<(int)(E_X / 4 / 256), 256>>>(x, xbh, xbl, (int)(E_X / 4));
    convert_split<<<(int)(E_WS / 4 / 256), 256>>>(w_hseq, whh, whl, (int)(E_WS / 4));
    convert_hi<<<(int)(E_W / 4 / 256), 256>>>(wq, wqh, (int)(E_W / 4));
    convert_hi<<<(int)(E_W / 4 / 256), 256>>>(wk, wkh, (int)(E_W / 4));
    convert_hi<<<(int)(E_W / 4 / 256), 256>>>(wv, wvh, (int)(E_W / 4));
    convert_hi<<<(int)(E_WS / 4 / 256), 256>>>(w_oseq, woh, (int)(E_WS / 4));

    // smem: 2 stages of (A_TOT + B_TOT)
    const int SM_A = 2 * (2 * 10240 + 2 * 8704);   // 75776  <0,0,1,128,1,1,1>
    const int SM_B = 2 * (10240 + 10240);          // 40960  <0,1,2,128,2,0,0>
    const int SM_C = 2 * (10240 + 10240);          // 40960  <0,1,0,128,2,0,0>
    const int SM_E = 2 * (8704 + 4608);            // 26624  <1,0,0,64,2,0,0>
    const int SM_F = 2 * (10240 + 4608);           // 29696  <0,0,3,64,0,0,0>

    cudaFuncSetAttribute(tgemm<0, 0, 1, 128, 1, 1, 1>, cudaFuncAttributeMaxDynamicSharedMemorySize, SM_A);
    cudaFuncSetAttribute(tgemm<0, 1, 2, 128, 2, 0, 0>, cudaFuncAttributeMaxDynamicSharedMemorySize, SM_B);
    cudaFuncSetAttribute(tgemm<0, 1, 0, 128, 2, 0, 0>, cudaFuncAttributeMaxDynamicSharedMemorySize, SM_C);
    cudaFuncSetAttribute(tgemm<1, 0, 0, 64, 2, 0, 0>,  cudaFuncAttributeMaxDynamicSharedMemorySize, SM_E);
    cudaFuncSetAttribute(tgemm<0, 0, 3, 64, 0, 0, 0>,  cudaFuncAttributeMaxDynamicSharedMemorySize, SM_F);

    // Stage A: xh = w_hseq @ x + b_hseq  (3-pass, pair out — feeds S precisely)
    tgemm<0, 0, 1, 128, 1, 1, 1><<<dim3(CDIM / 128, SEQ / 128, NB_), 256, SM_A>>>(
        whh, whl, xbh, xbl, nullptr, xhh, xhl,
        SEQ, CDIM, CDIM, 0, 0, sBT, 0, sBT, 0, 1,
        b_hseq, nullptr, 0, 0, 1.0f, SEQ);

    // Precise S = colsum(xh) @ wv^T + SEQ*bv  (fp32 path for the dominant term)
    colsum_xh<<<(NB_ * CDIM + 255) / 256, 256>>>(xhh, xhl, sxh);
    s_from_xh<<<(NB_ * CDIM) / 8, 256>>>(sxh, wv, bv, sv);

    // Stage B: q/k/v = xh_h @ W_h^T + bias  (1-pass, hi-only out)
    tgemm<0, 1, 2, 128, 2, 0, 0><<<dim3(CDIM / 128, (NB_ * SEQ) / 128, 1), 256, SM_B>>>(
        xhh, nullptr, wqh, nullptr, nullptr, qh, nullptr,
        CDIM, CDIM, CDIM, 0, 0, 0, 0, 0, 0, 1,
        bq, nullptr, 0, 0, 1.0f, CDIM);
    tgemm<0, 1, 2, 128, 2, 0, 0><<<dim3(CDIM / 128, (NB_ * SEQ) / 128, 1), 256, SM_B>>>(
        xhh, nullptr, wkh, nullptr, nullptr, kh, nullptr,
        CDIM, CDIM, CDIM, 0, 0, 0, 0, 0, 0, 1,
        bk, nullptr, 0, 0, 1.0f, CDIM);
    tgemm<0, 1, 2, 128, 2, 0, 0><<<dim3(CDIM / 128, (NB_ * SEQ) / 128, 1), 256, SM_B>>>(
        xhh, nullptr, wvh, nullptr, nullptr, vh, nullptr,
        CDIM, CDIM, CDIM, 0, 0, 0, 0, 0, 0, 1,
        bv, nullptr, 0, 0, 1.0f, CDIM);

    // Stage C: scores = (1/8) q.k  (1-pass, bf16 out)
    tgemm<0, 1, 0, 128, 2, 0, 0><<<dim3(SEQ / 128, SEQ / 128, NB_ * NH), 256, SM_C>>>(
        qh, nullptr, kh, nullptr, nullptr, attn, nullptr,
        CDIM, CDIM, SEQ, sBT, HD, sBT, HD, sAb, sAh_, NH,
        nullptr, nullptr, 0, 0, 0.125f, HD);

    // Stage D: softmax -> bf16 probs
    softmax_rows<<<NB_ * NH * SEQ, 256>>>(attn, pph);

    // Stage E: Z = P^T @ V  (1-pass, bf16 hi out)
    tgemm<1, 0, 0, 64, 2, 0, 0><<<dim3(1, SEQ / 128, NB_ * NH), 256, SM_E>>>(
        pph, nullptr, vh, nullptr, nullptr, zh, nullptr,
        SEQ, CDIM, HD, sAb, sAh_, sBT, HD, sZb, sZh_, NH,
        nullptr, nullptr, 0, 0, 1.0f, SEQ);

    // Stage F: out = wo_h @ Z_h + b_oseq*S  (1-pass; exact fp32 rank-1 term)
    tgemm<0, 0, 3, 64, 0, 0, 0><<<dim3(1, SEQ / 128, NB_ * NH), 256, SM_F>>>(
        woh, nullptr, zh, nullptr, out, nullptr, nullptr,
        SEQ, HD, CDIM, 0, 0, sZb, sZh_, sBT, HD, NH,
        b_oseq, sv, CDIM, HD, 1.0f, SEQ);
}